// round 6
// baseline (speedup 1.0000x reference)
#include <cuda_runtime.h>
#include <math.h>

#define NSER 4096
#define NTT  400
#define NPAIR (NSER/2)
#define LOG2PI 1.8378770664093453f

// scratch (static __device__ arrays: allocation-free)
__device__ float g_ll[NSER];
__device__ float g_Z[NTT * 5 * NSER];   // [t][k][n]  k: c0,c1,c2,su,yDy
__device__ float g_S[NTT * 6 * NSER];   // [t][j][n]  j: pa,pb,x0,x1,x2,x3

// ---------------- packed fp32x2 type (sm_103a) ----------------
struct F2 { unsigned long long v; };

__device__ __forceinline__ F2 f2pack(float lo, float hi) {
    F2 r; asm("mov.b64 %0,{%1,%2};" : "=l"(r.v) : "f"(lo), "f"(hi)); return r;
}
__device__ __forceinline__ F2 f2bc(float x) { return f2pack(x, x); }
__device__ __forceinline__ void f2un(F2 a, float& lo, float& hi) {
    asm("mov.b64 {%0,%1},%2;" : "=f"(lo), "=f"(hi) : "l"(a.v));
}
__device__ __forceinline__ F2 operator*(F2 a, F2 b) {
    F2 r; asm("mul.rn.f32x2 %0,%1,%2;" : "=l"(r.v) : "l"(a.v), "l"(b.v)); return r;
}
__device__ __forceinline__ F2 operator+(F2 a, F2 b) {
    F2 r; asm("add.rn.f32x2 %0,%1,%2;" : "=l"(r.v) : "l"(a.v), "l"(b.v)); return r;
}
__device__ __forceinline__ F2 f2neg(F2 a) {
    F2 r;
    asm("{.reg .b64 m; mov.b64 m, 0x8000000080000000; xor.b64 %0, %1, m;}"
        : "=l"(r.v) : "l"(a.v));
    return r;
}
__device__ __forceinline__ F2 operator-(F2 a, F2 b) { return a + f2neg(b); }
__device__ __forceinline__ F2 fm(F2 a, F2 b, F2 c) {
    F2 r; asm("fma.rn.f32x2 %0,%1,%2,%3;" : "=l"(r.v) : "l"(a.v), "l"(b.v), "l"(c.v)); return r;
}
// a*x + b*y + c*z   (and +w variant)
__device__ __forceinline__ F2 d3(F2 a, F2 x, F2 b, F2 y, F2 c, F2 z) {
    return fm(a, x, fm(b, y, c * z));
}
__device__ __forceinline__ F2 d3a(F2 a, F2 x, F2 b, F2 y, F2 c, F2 z, F2 w) {
    return fm(a, x, fm(b, y, fm(c, z, w)));
}

__device__ __forceinline__ float rcpa(float x) {
    float r; asm("rcp.approx.f32 %0,%1;" : "=f"(r) : "f"(x)); return r;
}
__device__ __forceinline__ float rsqa(float x) {
    float r; asm("rsqrt.approx.f32 %0,%1;" : "=f"(r) : "f"(x)); return r;
}

// ================= pre-pass: y[N,NT,9] -> Z[t][5][N] =================
__global__ void prepass(const float* __restrict__ y,
                        const float* __restrict__ l1f,
                        const float* __restrict__ l2f,
                        const float* __restrict__ logr)
{
    __shared__ float sWD[9], sdu[9], sDi[9];
    int lt = threadIdx.x;
    if (lt < 9) {
        int m = lt % 3;
        float w = (m == 0) ? 1.f : l1f[(lt / 3) * 2 + (m - 1)];
        float u = (lt == 0) ? 1.f : l2f[lt - 1];
        float rv = expf(logr[lt]);
        float di = 1.0f / (rv + 1e-6f);
        sDi[lt] = di; sWD[lt] = w * di; sdu[lt] = u * di;
    }
    __syncthreads();
    int tid = blockIdx.x * blockDim.x + threadIdx.x;   // [0, NSER*NTT)
    int n = tid & (NSER - 1);
    int t = tid >> 12;
    const float* yp = y + ((size_t)n * NTT + t) * 9;
    float c0 = 0.f, c1 = 0.f, c2 = 0.f, su = 0.f, yd = 0.f;
#pragma unroll
    for (int o = 0; o < 9; o++) {
        float yv = yp[o];
        float wdv = sWD[o] * yv;
        if (o < 3) c0 += wdv; else if (o < 6) c1 += wdv; else c2 += wdv;
        su += sdu[o] * yv;
        yd += sDi[o] * yv * yv;
    }
    int base = t * 5 * NSER + n;
    g_Z[base]            = c0;
    g_Z[base + NSER]     = c1;
    g_Z[base + 2 * NSER] = c2;
    g_Z[base + 3 * NSER] = su;
    g_Z[base + 4 * NSER] = yd;
}

// ================= main sequential filter, 2 series per thread =================
__global__ __launch_bounds__(32)
void kf_main(const float* __restrict__ B1,
             const float* __restrict__ b2p,
             const float* __restrict__ l1f,
             const float* __restrict__ l2f,
             const float* __restrict__ logq,
             const float* __restrict__ logr,
             const float* __restrict__ g0p,
             const float* __restrict__ gcp)
{
    const int i = blockIdx.x * 32 + threadIdx.x;   // pair index [0, 2048)

    // -------- scalar constant setup (uniform across threads) --------
    float Bs[9];
#pragma unroll
    for (int k = 0; k < 9; k++) Bs[k] = B1[k];
    const float b2s = b2p[0];
    const float w1 = l1f[0], w2 = l1f[1], w4 = l1f[2], w5 = l1f[3], w7 = l1f[4], w8 = l1f[5];
    float ws[9];
    ws[0] = 1.f; ws[1] = w1; ws[2] = w2; ws[3] = 1.f; ws[4] = w4; ws[5] = w5;
    ws[6] = 1.f; ws[7] = w7; ws[8] = w8;
    float us[9];
    us[0] = 1.f;
#pragma unroll
    for (int k = 1; k < 9; k++) us[k] = l2f[k - 1];

    float G0s = 0.f, G1s = 0.f, G2s = 0.f;
    float GR0s = 0.f, GR1s = 0.f, GR2s = 0.f;
    float logdetD = 0.f, alphas = 0.f, rhos = 0.f;
#pragma unroll
    for (int o = 0; o < 9; o++) {
        float rv = expf(logr[o]);
        float Dv = rv + 1e-6f;
        float di = 1.0f / Dv;
        logdetD += logf(Dv);
        float gterm = ws[o] * ws[o] * di;
        float grterm = ws[o] * ws[o] * rv * di * di;
        if (o < 3)      { G0s += gterm; GR0s += grterm; }
        else if (o < 6) { G1s += gterm; GR1s += grterm; }
        else            { G2s += gterm; GR2s += grterm; }
        alphas += us[o] * us[o] * di;
        rhos   += us[o] * us[o] * rv * di * di;
    }
    const float Clls = -0.5f * 9.0f * LOG2PI - 0.5f * logdetD;

    // -------- packed constants --------
    const F2 B0 = f2bc(Bs[0]), B1c = f2bc(Bs[1]), B2 = f2bc(Bs[2]);
    const F2 B3 = f2bc(Bs[3]), B4 = f2bc(Bs[4]), B5 = f2bc(Bs[5]);
    const F2 B6 = f2bc(Bs[6]), B7 = f2bc(Bs[7]), B8 = f2bc(Bs[8]);
    const F2 b2c = f2bc(b2s), b2sq = f2bc(b2s * b2s);
    const F2 qv0 = f2bc(expf(logq[0])), qv1 = f2bc(expf(logq[1]));
    const F2 qv2 = f2bc(expf(logq[2])), qv3 = f2bc(expf(logq[3]));
    const F2 G0c = f2bc(G0s), G1c = f2bc(G1s), G2c = f2bc(G2s);
    const F2 Gn0 = f2bc(-G0s), Gn1 = f2bc(-G1s), Gn2 = f2bc(-G2s);
    const F2 GR0 = f2bc(GR0s), GR1 = f2bc(GR1s), GR2 = f2bc(GR2s);
    const F2 ALP = f2bc(alphas), ALPN = f2bc(-alphas), RHON = f2bc(-rhos);
    const F2 ONE = f2bc(1.0f), TWO = f2bc(2.0f), HALF = f2bc(0.5f);
    const F2 CLL = f2bc(Clls), NEG2 = f2bc(-2.0f), EPSc = f2bc(1e-9f);
    const F2 g0c = f2bc(g0p[0]);
    const F2 gc0 = f2bc(gcp[0]), gc1 = f2bc(gcp[1]), gc2 = f2bc(gcp[2]);

    // -------- packed state --------
    F2 e0 = f2bc(0.f), e1 = f2bc(0.f), e2 = f2bc(0.f), e3 = f2bc(0.f);
    F2 p00 = f2bc(1000.f), p01 = f2bc(0.f), p02 = f2bc(0.f), p03 = f2bc(0.f);
    F2 p11 = f2bc(1000.f), p12 = f2bc(0.f), p13 = f2bc(0.f);
    F2 p22 = f2bc(1000.f), p23 = f2bc(0.f), p33 = f2bc(1000.f);
    F2 pr0 = f2bc(0.99f), pr1 = f2bc(0.01f);
    float llA = 0.f, llB = 0.f;

    const F2* Zp = reinterpret_cast<const F2*>(g_Z);
    F2* Sp = reinterpret_cast<F2*>(g_S);

    // initial Z load (t = 0)
    F2 zc0 = Zp[0 * NPAIR + i];
    F2 zc1 = Zp[1 * NPAIR + i];
    F2 zc2 = Zp[2 * NPAIR + i];
    F2 zsu = Zp[3 * NPAIR + i];
    F2 zyd = Zp[4 * NPAIR + i];

#pragma unroll 1
    for (int t = 0; t < NTT; t++) {
        // prefetch next timestep's transformed observations
        F2 nz0, nz1, nz2, nz3, nz4;
        if (t + 1 < NTT) {
            int zb = (t + 1) * 5 * NPAIR + i;
            nz0 = Zp[zb]; nz1 = Zp[zb + NPAIR]; nz2 = Zp[zb + 2 * NPAIR];
            nz3 = Zp[zb + 3 * NPAIR]; nz4 = Zp[zb + 4 * NPAIR];
        }

        // regime-1 stay probability (sigmoid of linear form of current state)
        F2 xg = d3a(gc0, e0, gc1, e1, gc2, e2, g0c);

        // ---------- predict ----------
        F2 ep0 = d3(B0, e0, B1c, e1, B2, e2);
        F2 ep1 = d3(B3, e0, B4, e1, B5, e2);
        F2 ep2 = d3(B6, e0, B7, e1, B8, e2);
        F2 ep3 = b2c * e3;

        F2 T00 = d3(B0, p00, B1c, p01, B2, p02);
        F2 T01 = d3(B0, p01, B1c, p11, B2, p12);
        F2 T02 = d3(B0, p02, B1c, p12, B2, p22);
        F2 T10 = d3(B3, p00, B4, p01, B5, p02);
        F2 T11 = d3(B3, p01, B4, p11, B5, p12);
        F2 T12 = d3(B3, p02, B4, p12, B5, p22);
        F2 T20 = d3(B6, p00, B7, p01, B8, p02);
        F2 T21 = d3(B6, p01, B7, p11, B8, p12);
        F2 T22 = d3(B6, p02, B7, p12, B8, p22);

        F2 s00 = d3a(T00, B0, T01, B1c, T02, B2, qv0);
        F2 s01 = d3(T00, B3, T01, B4, T02, B5);
        F2 s02 = d3(T00, B6, T01, B7, T02, B8);
        F2 s11 = d3a(T10, B3, T11, B4, T12, B5, qv1);
        F2 s12 = d3(T10, B6, T11, B7, T12, B8);
        F2 s22 = d3a(T20, B6, T21, B7, T22, B8, qv2);
        F2 s03 = b2c * d3(B0, p03, B1c, p13, B2, p23);
        F2 s13 = b2c * d3(B3, p03, B4, p13, B5, p23);
        F2 s23 = b2c * d3(B6, p03, B7, p13, B8, p23);
        F2 s33 = fm(b2sq, p33, qv3);

        // ========== Regime 1: Ntil = I + S3*diag(G), cofactors, det ==========
        F2 N00 = fm(s00, G0c, ONE), N01 = s01 * G1c, N02 = s02 * G2c;
        F2 N10 = s01 * G0c, N11 = fm(s11, G1c, ONE), N12 = s12 * G2c;
        F2 N20 = s02 * G0c, N21 = s12 * G1c, N22 = fm(s22, G2c, ONE);

        F2 c00 = N11 * N22 - N12 * N21;
        F2 c01 = N02 * N21 - N01 * N22;
        F2 c02 = N01 * N12 - N02 * N11;
        F2 c10 = N12 * N20 - N10 * N22;
        F2 c11 = N00 * N22 - N02 * N20;
        F2 c12 = N02 * N10 - N00 * N12;
        F2 c20 = N10 * N21 - N11 * N20;
        F2 c21 = N01 * N20 - N00 * N21;
        F2 c22 = N00 * N11 - N01 * N10;
        F2 det = d3(N00, c00, N01, c10, N02, c20);   // det(F1)/det(D)

        F2 beta = fm(s33, ALP, ONE);                 // det(F2)/det(D)

        // -------- per-lane MUFU: reciprocals & rsqrt for both regimes --------
        float dlo, dhi, blo, bhi;
        f2un(det, dlo, dhi); f2un(beta, blo, bhi);
        F2 idet  = f2pack(rcpa(dlo), rcpa(dhi));
        F2 rdet  = f2pack(rsqa(dlo), rsqa(dhi));
        F2 binv  = f2pack(rcpa(blo), rcpa(bhi));
        F2 rbeta = f2pack(rsqa(blo), rsqa(bhi));

        // E = Ntil^{-1} S3
        F2 E00 = d3(c00, s00, c01, s01, c02, s02) * idet;
        F2 E01 = d3(c00, s01, c01, s11, c02, s12) * idet;
        F2 E02 = d3(c00, s02, c01, s12, c02, s22) * idet;
        F2 E10 = d3(c10, s00, c11, s01, c12, s02) * idet;
        F2 E11 = d3(c10, s01, c11, s11, c12, s12) * idet;
        F2 E12 = d3(c10, s02, c11, s12, c12, s22) * idet;
        F2 E20 = d3(c20, s00, c21, s01, c22, s02) * idet;
        F2 E21 = d3(c20, s01, c21, s11, c22, s12) * idet;
        F2 E22 = d3(c20, s02, c21, s12, c22, s22) * idet;

        // innovation summaries from pre-pass:  t_k = c_k - G_k*ep_k
        F2 t0 = fm(Gn0, ep0, zc0);
        F2 t1 = fm(Gn1, ep1, zc1);
        F2 t2 = fm(Gn2, ep2, zc2);
        // vDv = yDy - 2*sum c_k ep_k + sum G_k ep_k^2
        F2 h0 = fm(G0c, ep0, zc0 * NEG2);
        F2 h1 = fm(G1c, ep1, zc1 * NEG2);
        F2 h2 = fm(G2c, ep2, zc2 * NEG2);
        F2 vDv = fm(ep0, h0, fm(ep1, h1, fm(ep2, h2, zyd)));

        F2 m0 = d3(E00, t0, E01, t1, E02, t2);
        F2 m1 = d3(E10, t0, E11, t1, E12, t2);
        F2 m2 = d3(E20, t0, E21, t1, E22, t2);
        F2 quad = d3(t0, m0, t1, m1, t2, m2);

        // J = I - diag(G)*E
        F2 J00 = fm(Gn0, E00, ONE), J01 = Gn0 * E01, J02 = Gn0 * E02;
        F2 J10 = Gn1 * E10, J11 = fm(Gn1, E11, ONE), J12 = Gn1 * E12;
        F2 J20 = Gn2 * E20, J21 = Gn2 * E21, J22 = fm(Gn2, E22, ONE);

        // H = P_pred[:, :3] * J
        F2 H00 = d3(s00, J00, s01, J10, s02, J20);
        F2 H01 = d3(s00, J01, s01, J11, s02, J21);
        F2 H02 = d3(s00, J02, s01, J12, s02, J22);
        F2 H10 = d3(s01, J00, s11, J10, s12, J20);
        F2 H11 = d3(s01, J01, s11, J11, s12, J21);
        F2 H12 = d3(s01, J02, s11, J12, s12, J22);
        F2 H20 = d3(s02, J00, s12, J10, s22, J20);
        F2 H21 = d3(s02, J01, s12, J11, s22, J21);
        F2 H22 = d3(s02, J02, s12, J12, s22, J22);
        F2 H30 = d3(s03, J00, s13, J10, s23, J20);
        F2 H31 = d3(s03, J01, s13, J11, s23, J21);
        F2 H32 = d3(s03, J02, s13, J12, s23, J22);

        // eta1 = eta_pred + H t
        F2 q10 = d3a(H00, t0, H01, t1, H02, t2, ep0);
        F2 q11 = d3a(H10, t0, H11, t1, H12, t2, ep1);
        F2 q12 = d3a(H20, t0, H21, t1, H22, t2, ep2);
        F2 q13 = d3a(H30, t0, H31, t1, H32, t2, ep3);

        // HGn = -H*diag(G)   (so all Joseph terms become pure adds)
        F2 HGn00 = H00 * Gn0, HGn01 = H01 * Gn1, HGn02 = H02 * Gn2;
        F2 HGn10 = H10 * Gn0, HGn11 = H11 * Gn1, HGn12 = H12 * Gn2;
        F2 HGn20 = H20 * Gn0, HGn21 = H21 * Gn1, HGn22 = H22 * Gn2;
        F2 HGn30 = H30 * Gn0, HGn31 = H31 * Gn1, HGn32 = H32 * Gn2;

        // AP = (I - K L1) P_pred
        F2 AP00 = d3a(HGn00, s00, HGn01, s01, HGn02, s02, s00);
        F2 AP01 = d3a(HGn00, s01, HGn01, s11, HGn02, s12, s01);
        F2 AP02 = d3a(HGn00, s02, HGn01, s12, HGn02, s22, s02);
        F2 AP03 = d3a(HGn00, s03, HGn01, s13, HGn02, s23, s03);
        F2 AP10 = d3a(HGn10, s00, HGn11, s01, HGn12, s02, s01);
        F2 AP11 = d3a(HGn10, s01, HGn11, s11, HGn12, s12, s11);
        F2 AP12 = d3a(HGn10, s02, HGn11, s12, HGn12, s22, s12);
        F2 AP13 = d3a(HGn10, s03, HGn11, s13, HGn12, s23, s13);
        F2 AP20 = d3a(HGn20, s00, HGn21, s01, HGn22, s02, s02);
        F2 AP21 = d3a(HGn20, s01, HGn21, s11, HGn22, s12, s12);
        F2 AP22 = d3a(HGn20, s02, HGn21, s12, HGn22, s22, s22);
        F2 AP23 = d3a(HGn20, s03, HGn21, s13, HGn22, s23, s23);
        F2 AP30 = d3a(HGn30, s00, HGn31, s01, HGn32, s02, s03);
        F2 AP31 = d3a(HGn30, s01, HGn31, s11, HGn32, s12, s13);
        F2 AP32 = d3a(HGn30, s02, HGn31, s12, HGn32, s22, s23);
        F2 AP33 = d3a(HGn30, s03, HGn31, s13, HGn32, s23, s33);

        // Hr = H*diag(GR)
        F2 Hr00 = H00 * GR0, Hr01 = H01 * GR1, Hr02 = H02 * GR2;
        F2 Hr10 = H10 * GR0, Hr11 = H11 * GR1, Hr12 = H12 * GR2;
        F2 Hr20 = H20 * GR0, Hr21 = H21 * GR1, Hr22 = H22 * GR2;
        F2 Hr30 = H30 * GR0, Hr31 = H31 * GR1, Hr32 = H32 * GR2;

        // P1 = AP + AP*HGn^T + Hr*H^T  (upper triangle)
        F2 P1_00 = fm(AP00, HGn00, fm(AP01, HGn01, fm(AP02, HGn02,
                   fm(Hr00, H00, fm(Hr01, H01, fm(Hr02, H02, AP00))))));
        F2 P1_01 = fm(AP00, HGn10, fm(AP01, HGn11, fm(AP02, HGn12,
                   fm(Hr00, H10, fm(Hr01, H11, fm(Hr02, H12, AP01))))));
        F2 P1_02 = fm(AP00, HGn20, fm(AP01, HGn21, fm(AP02, HGn22,
                   fm(Hr00, H20, fm(Hr01, H21, fm(Hr02, H22, AP02))))));
        F2 P1_03 = fm(AP00, HGn30, fm(AP01, HGn31, fm(AP02, HGn32,
                   fm(Hr00, H30, fm(Hr01, H31, fm(Hr02, H32, AP03))))));
        F2 P1_11 = fm(AP10, HGn10, fm(AP11, HGn11, fm(AP12, HGn12,
                   fm(Hr10, H10, fm(Hr11, H11, fm(Hr12, H12, AP11))))));
        F2 P1_12 = fm(AP10, HGn20, fm(AP11, HGn21, fm(AP12, HGn22,
                   fm(Hr10, H20, fm(Hr11, H21, fm(Hr12, H22, AP12))))));
        F2 P1_13 = fm(AP10, HGn30, fm(AP11, HGn31, fm(AP12, HGn32,
                   fm(Hr10, H30, fm(Hr11, H31, fm(Hr12, H32, AP13))))));
        F2 P1_22 = fm(AP20, HGn20, fm(AP21, HGn21, fm(AP22, HGn22,
                   fm(Hr20, H20, fm(Hr21, H21, fm(Hr22, H22, AP22))))));
        F2 P1_23 = fm(AP20, HGn30, fm(AP21, HGn31, fm(AP22, HGn32,
                   fm(Hr20, H30, fm(Hr21, H31, fm(Hr22, H32, AP23))))));
        F2 P1_33 = fm(AP30, HGn30, fm(AP31, HGn31, fm(AP32, HGn32,
                   fm(Hr30, H30, fm(Hr31, H31, fm(Hr32, H32, AP33))))));

        // ========== Regime 2: rank-1 Sherman-Morrison ==========
        F2 tau = fm(ALPN, ep3, zsu);
        F2 vDv2 = fm(ep3, fm(ALP, ep3, zsu * NEG2), zyd);
        F2 q2q = (s33 * (tau * tau)) * binv;
        F2 gk = tau * binv;
        F2 q20 = fm(s03, gk, ep0);
        F2 q21 = fm(s13, gk, ep1);
        F2 q22 = fm(s23, gk, ep2);
        F2 q23 = fm(s33, gk, ep3);

        F2 cc = ALP * binv;
        F2 kap = fm(cc, TWO - cc * s33, RHON * (binv * binv));
        F2 kn = f2neg(kap);
        F2 k0 = kn * s03, k1 = kn * s13, k2 = kn * s23, k3 = kn * s33;
        F2 P2_00 = fm(k0, s03, s00);
        F2 P2_01 = fm(k0, s13, s01);
        F2 P2_02 = fm(k0, s23, s02);
        F2 P2_03 = fm(k0, s33, s03);
        F2 P2_11 = fm(k1, s13, s11);
        F2 P2_12 = fm(k1, s23, s12);
        F2 P2_13 = fm(k1, s33, s13);
        F2 P2_22 = fm(k2, s23, s22);
        F2 P2_23 = fm(k2, s33, s23);
        F2 P2_33 = fm(k3, s33, s33);

        // -------- likelihoods & mixing (per-lane MUFU region) --------
        // exp(ll) = exp(Cll - 0.5*(vDv - quad)) / sqrt(det-ratio)
        F2 arg1 = fm(quad - vDv, HALF, CLL);
        F2 arg2 = fm(q2q - vDv2, HALF, CLL);
        float a1l, a1h, a2l, a2h, xl, xh;
        f2un(arg1, a1l, a1h); f2un(arg2, a2l, a2h); f2un(xg, xl, xh);
        F2 el1 = f2pack(__expf(a1l), __expf(a1h)) * rdet;
        F2 el2 = f2pack(__expf(a2l), __expf(a2h)) * rbeta;
        F2 p11s = f2pack(rcpa(1.0f + __expf(-xl)), rcpa(1.0f + __expf(-xh)));

        F2 g1 = pr0 * p11s;
        F2 num1 = el1 * g1;
        F2 g2 = (pr0 + pr1) - g1;
        F2 num2 = el2 * g2;
        F2 marg = (num1 + num2) + EPSc;
        float mlo, mhi;
        f2un(marg, mlo, mhi);
        llA += __logf(mlo);
        llB += __logf(mhi);
        F2 im = f2pack(rcpa(mlo), rcpa(mhi));
        F2 pa = num1 * im;
        F2 pb = num2 * im;

        F2 x0 = fm(pa, q10, pb * q20);
        F2 x1 = fm(pa, q11, pb * q21);
        F2 x2 = fm(pa, q12, pb * q22);
        F2 x3 = fm(pa, q13, pb * q23);

        F2 d10 = q10 - x0, d11 = q11 - x1, d12 = q12 - x2, d13 = q13 - x3;
        F2 d20 = q20 - x0, d21 = q21 - x1, d22 = q22 - x2, d23 = q23 - x3;

        p00 = fm(pa, fm(d10, d10, P1_00), pb * fm(d20, d20, P2_00));
        p01 = fm(pa, fm(d10, d11, P1_01), pb * fm(d20, d21, P2_01));
        p02 = fm(pa, fm(d10, d12, P1_02), pb * fm(d20, d22, P2_02));
        p03 = fm(pa, fm(d10, d13, P1_03), pb * fm(d20, d23, P2_03));
        p11 = fm(pa, fm(d11, d11, P1_11), pb * fm(d21, d21, P2_11));
        p12 = fm(pa, fm(d11, d12, P1_12), pb * fm(d21, d22, P2_12));
        p13 = fm(pa, fm(d11, d13, P1_13), pb * fm(d21, d23, P2_13));
        p22 = fm(pa, fm(d12, d12, P1_22), pb * fm(d22, d22, P2_22));
        p23 = fm(pa, fm(d12, d13, P1_23), pb * fm(d22, d23, P2_23));
        p33 = fm(pa, fm(d13, d13, P1_33), pb * fm(d23, d23, P2_33));

        // coalesced packed stores of mixing results (expanded in post-pass)
        int sb = t * 6 * NPAIR + i;
        Sp[sb]             = pa;
        Sp[sb + NPAIR]     = pb;
        Sp[sb + 2 * NPAIR] = x0;
        Sp[sb + 3 * NPAIR] = x1;
        Sp[sb + 4 * NPAIR] = x2;
        Sp[sb + 5 * NPAIR] = x3;

        // commit state
        e0 = x0; e1 = x1; e2 = x2; e3 = x3;
        pr0 = pa; pr1 = pb;
        zc0 = nz0; zc1 = nz1; zc2 = nz2; zsu = nz3; zyd = nz4;
    }

    g_ll[2 * i]     = llA;
    g_ll[2 * i + 1] = llB;
}

// ================= post-pass: S[t][6][N] -> probs[N,NT,2], y_pred[N,NT,9] =================
__global__ void postpass(const float* __restrict__ l1f,
                         const float* __restrict__ l2f,
                         float* __restrict__ out)
{
    __shared__ float sh[6][32][33];
    const int n0 = blockIdx.x * 32, t0 = blockIdx.y * 32;
    const int tx = threadIdx.x, ty = threadIdx.y;

    int tA = t0 + ty;
    if (tA < NTT) {
#pragma unroll
        for (int j = 0; j < 6; j++)
            sh[j][ty][tx] = g_S[(tA * 6 + j) * NSER + n0 + tx];
    }
    __syncthreads();

    int tt = t0 + tx;
    if (tt < NTT) {
        int n = n0 + ty;
        float pa = sh[0][tx][ty], pb = sh[1][tx][ty];
        float x0 = sh[2][tx][ty], x1 = sh[3][tx][ty];
        float x2 = sh[4][tx][ty], x3 = sh[5][tx][ty];

        size_t idx = (size_t)n * NTT + tt;
        float* probs = out + 1;
        probs[idx * 2]     = pa;
        probs[idx * 2 + 1] = pb;

        float w1 = l1f[0], w2 = l1f[1], w4 = l1f[2], w5 = l1f[3], w7 = l1f[4], w8 = l1f[5];
        float pe0 = pa * x0, pe1 = pa * x1, pe2 = pa * x2;
        float a3 = pb * x3;
        float* yo = out + 1 + (size_t)NSER * NTT * 2 + idx * 9;
        yo[0] = pe0 + a3;
        yo[1] = w1 * pe0 + l2f[0] * a3;
        yo[2] = w2 * pe0 + l2f[1] * a3;
        yo[3] = pe1 + l2f[2] * a3;
        yo[4] = w4 * pe1 + l2f[3] * a3;
        yo[5] = w5 * pe1 + l2f[4] * a3;
        yo[6] = pe2 + l2f[5] * a3;
        yo[7] = w7 * pe2 + l2f[6] * a3;
        yo[8] = w8 * pe2 + l2f[7] * a3;
    }
}

// Deterministic fixed-order reduction of per-series log-likelihoods.
__global__ void reduce_ll(float* __restrict__ out)
{
    __shared__ double sh[256];
    int t = threadIdx.x;
    double a = 0.0;
#pragma unroll
    for (int i = 0; i < 16; i++) a += (double)g_ll[t * 16 + i];
    sh[t] = a;
    __syncthreads();
#pragma unroll
    for (int s = 128; s > 0; s >>= 1) {
        if (t < s) sh[t] += sh[t + s];
        __syncthreads();
    }
    if (t == 0) out[0] = (float)(-sh[0]);
}

extern "C" void kernel_launch(void* const* d_in, const int* in_sizes, int n_in,
                              void* d_out, int out_size)
{
    (void)in_sizes; (void)n_in; (void)out_size;
    const float* y    = (const float*)d_in[0];
    const float* B1s1 = (const float*)d_in[1];
    const float* B1s2 = (const float*)d_in[2];
    const float* l1f  = (const float*)d_in[3];
    const float* l2f  = (const float*)d_in[4];
    const float* logq = (const float*)d_in[5];
    const float* logr = (const float*)d_in[6];
    const float* g0   = (const float*)d_in[7];
    const float* gc   = (const float*)d_in[8];
    float* out = (float*)d_out;

    prepass<<<(NSER * NTT) / 256, 256>>>(y, l1f, l2f, logr);
    kf_main<<<NPAIR / 32, 32>>>(B1s1, B1s2, l1f, l2f, logq, logr, g0, gc);
    postpass<<<dim3(NSER / 32, (NTT + 31) / 32), dim3(32, 32)>>>(l1f, l2f, out);
    reduce_ll<<<1, 256>>>(out);
}

// round 9
// speedup vs baseline: 1.0785x; 1.0785x over previous
#include <cuda_runtime.h>
#include <math.h>

#define NSER 4096
#define NTT  400
#define LOG2PI 1.8378770664093453f

// scratch (static __device__ arrays: allocation-free)
__device__ float g_ll[NSER];
__device__ float g_Z[NTT * 5 * NSER];   // [t][k][n]  k: c0,c1,c2,su,yDy
__device__ float g_S[NTT * 6 * NSER];   // [t][j][n]  j: pa,pb,x0,x1,x2,x3

__device__ __forceinline__ float rcpa(float x) {
    float r; asm("rcp.approx.f32 %0,%1;" : "=f"(r) : "f"(x)); return r;
}
__device__ __forceinline__ float rsqa(float x) {
    float r; asm("rsqrt.approx.f32 %0,%1;" : "=f"(r) : "f"(x)); return r;
}

// ================= pre-pass: y[N,NT,9] -> Z[t][5][N] =================
__global__ void prepass(const float* __restrict__ y,
                        const float* __restrict__ l1f,
                        const float* __restrict__ l2f,
                        const float* __restrict__ logr)
{
    __shared__ float sWD[9], sdu[9], sDi[9];
    int lt = threadIdx.x;
    if (lt < 9) {
        int m = lt % 3;
        float w = (m == 0) ? 1.f : l1f[(lt / 3) * 2 + (m - 1)];
        float u = (lt == 0) ? 1.f : l2f[lt - 1];
        float rv = expf(logr[lt]);
        float di = 1.0f / (rv + 1e-6f);
        sDi[lt] = di; sWD[lt] = w * di; sdu[lt] = u * di;
    }
    __syncthreads();
    int tid = blockIdx.x * blockDim.x + threadIdx.x;   // [0, NSER*NTT)
    int n = tid & (NSER - 1);
    int t = tid >> 12;
    const float* yp = y + ((size_t)n * NTT + t) * 9;
    float c0 = 0.f, c1 = 0.f, c2 = 0.f, su = 0.f, yd = 0.f;
#pragma unroll
    for (int o = 0; o < 9; o++) {
        float yv = yp[o];
        float wdv = sWD[o] * yv;
        if (o < 3) c0 += wdv; else if (o < 6) c1 += wdv; else c2 += wdv;
        su += sdu[o] * yv;
        yd += sDi[o] * yv * yv;
    }
    int base = t * 5 * NSER + n;
    g_Z[base]            = c0;
    g_Z[base + NSER]     = c1;
    g_Z[base + 2 * NSER] = c2;
    g_Z[base + 3 * NSER] = su;
    g_Z[base + 4 * NSER] = yd;
}

// ================= main sequential filter (scalar, 1 series/thread) =================
__global__ __launch_bounds__(32)
void kf_main(const float* __restrict__ B1,
             const float* __restrict__ b2p,
             const float* __restrict__ l1f,
             const float* __restrict__ l2f,
             const float* __restrict__ logq,
             const float* __restrict__ logr,
             const float* __restrict__ g0p,
             const float* __restrict__ gcp)
{
    const int n = blockIdx.x * 32 + threadIdx.x;   // series [0, 4096)

    // -------- constant precompute (uniform across threads) --------
    float Bm[9];
#pragma unroll
    for (int k = 0; k < 9; k++) Bm[k] = B1[k];
    const float b2 = b2p[0];
    const float w1 = l1f[0], w2 = l1f[1], w4 = l1f[2], w5 = l1f[3], w7 = l1f[4], w8 = l1f[5];
    float ws[9];
    ws[0] = 1.f; ws[1] = w1; ws[2] = w2; ws[3] = 1.f; ws[4] = w4; ws[5] = w5;
    ws[6] = 1.f; ws[7] = w7; ws[8] = w8;
    float us[9];
    us[0] = 1.f;
#pragma unroll
    for (int k = 1; k < 9; k++) us[k] = l2f[k - 1];

    float G0 = 0.f, G1 = 0.f, G2 = 0.f;
    float logdetD = 0.f, alpha = 0.f;
#pragma unroll
    for (int o = 0; o < 9; o++) {
        float rv = expf(logr[o]);
        float Dv = rv + 1e-6f;
        float di = 1.0f / Dv;
        logdetD += logf(Dv);
        float gterm = ws[o] * ws[o] * di;
        if (o < 3)      G0 += gterm;
        else if (o < 6) G1 += gterm;
        else            G2 += gterm;
        alpha += us[o] * us[o] * di;
    }
    const float Cll = -0.5f * 9.0f * LOG2PI - 0.5f * logdetD;
    const float qv0 = expf(logq[0]), qv1 = expf(logq[1]);
    const float qv2 = expf(logq[2]), qv3 = expf(logq[3]);
    const float b2q = b2 * b2;
    const float g0 = g0p[0], gc0 = gcp[0], gc1 = gcp[1], gc2 = gcp[2];

    // -------- state --------
    float e0 = 0.f, e1 = 0.f, e2 = 0.f, e3 = 0.f;
    float p00 = 1000.f, p01 = 0.f, p02 = 0.f, p03 = 0.f;
    float p11v = 1000.f, p12 = 0.f, p13 = 0.f;
    float p22 = 1000.f, p23 = 0.f, p33 = 1000.f;
    float pr0 = 0.99f, pr1 = 0.01f;
    float llacc = 0.f;

    const float* Zb = g_Z + n;
    float* Sb = g_S + n;

    float zc0 = Zb[0], zc1 = Zb[NSER], zc2 = Zb[2 * NSER];
    float zsu = Zb[3 * NSER], zyd = Zb[4 * NSER];

#pragma unroll 1
    for (int t = 0; t < NTT; t++) {
        // prefetch next timestep's transformed observations
        float nz0, nz1, nz2, nz3, nz4;
        if (t + 1 < NTT) {
            const float* Zt = Zb + (t + 1) * 5 * NSER;
            nz0 = Zt[0]; nz1 = Zt[NSER]; nz2 = Zt[2 * NSER];
            nz3 = Zt[3 * NSER]; nz4 = Zt[4 * NSER];
        }

        // regime-1 stay probability
        float xg = g0 + gc0 * e0 + gc1 * e1 + gc2 * e2;
        float p11s = rcpa(1.0f + __expf(-xg));

        // ---------- predict ----------
        float ep0 = Bm[0] * e0 + Bm[1] * e1 + Bm[2] * e2;
        float ep1 = Bm[3] * e0 + Bm[4] * e1 + Bm[5] * e2;
        float ep2 = Bm[6] * e0 + Bm[7] * e1 + Bm[8] * e2;
        float ep3 = b2 * e3;

        float T00 = Bm[0] * p00 + Bm[1] * p01 + Bm[2] * p02;
        float T01 = Bm[0] * p01 + Bm[1] * p11v + Bm[2] * p12;
        float T02 = Bm[0] * p02 + Bm[1] * p12 + Bm[2] * p22;
        float T10 = Bm[3] * p00 + Bm[4] * p01 + Bm[5] * p02;
        float T11 = Bm[3] * p01 + Bm[4] * p11v + Bm[5] * p12;
        float T12 = Bm[3] * p02 + Bm[4] * p12 + Bm[5] * p22;
        float T20 = Bm[6] * p00 + Bm[7] * p01 + Bm[8] * p02;
        float T21 = Bm[6] * p01 + Bm[7] * p11v + Bm[8] * p12;
        float T22 = Bm[6] * p02 + Bm[7] * p12 + Bm[8] * p22;

        float s00 = T00 * Bm[0] + T01 * Bm[1] + T02 * Bm[2] + qv0;
        float s01 = T00 * Bm[3] + T01 * Bm[4] + T02 * Bm[5];
        float s02 = T00 * Bm[6] + T01 * Bm[7] + T02 * Bm[8];
        float s11 = T10 * Bm[3] + T11 * Bm[4] + T12 * Bm[5] + qv1;
        float s12 = T10 * Bm[6] + T11 * Bm[7] + T12 * Bm[8];
        float s22 = T20 * Bm[6] + T21 * Bm[7] + T22 * Bm[8] + qv2;
        float s03 = b2 * (Bm[0] * p03 + Bm[1] * p13 + Bm[2] * p23);
        float s13 = b2 * (Bm[3] * p03 + Bm[4] * p13 + Bm[5] * p23);
        float s23 = b2 * (Bm[6] * p03 + Bm[7] * p13 + Bm[8] * p23);
        float s33 = b2q * p33 + qv3;

        // ========== Regime 1: rank-3 Woodbury ==========
        float N00 = 1.f + s00 * G0, N01 = s01 * G1, N02 = s02 * G2;
        float N10 = s01 * G0, N11 = 1.f + s11 * G1, N12 = s12 * G2;
        float N20 = s02 * G0, N21 = s12 * G1, N22 = 1.f + s22 * G2;

        float c00 = N11 * N22 - N12 * N21;
        float c01 = N02 * N21 - N01 * N22;
        float c02 = N01 * N12 - N02 * N11;
        float c10 = N12 * N20 - N10 * N22;
        float c11 = N00 * N22 - N02 * N20;
        float c12 = N02 * N10 - N00 * N12;
        float c20 = N10 * N21 - N11 * N20;
        float c21 = N01 * N20 - N00 * N21;
        float c22 = N00 * N11 - N01 * N10;
        float det = N00 * c00 + N01 * c10 + N02 * c20;   // det(F1)/det(D)
        float idet = rcpa(det);
        float rdet = rsqa(det);

        // E = Ntil^{-1} S3 (fold idet into cofactors)
        float a00 = c00 * idet, a01 = c01 * idet, a02 = c02 * idet;
        float a10 = c10 * idet, a11 = c11 * idet, a12 = c12 * idet;
        float a20 = c20 * idet, a21 = c21 * idet, a22 = c22 * idet;
        float E00 = a00 * s00 + a01 * s01 + a02 * s02;
        float E01 = a00 * s01 + a01 * s11 + a02 * s12;
        float E02 = a00 * s02 + a01 * s12 + a02 * s22;
        float E10 = a10 * s00 + a11 * s01 + a12 * s02;
        float E11 = a10 * s01 + a11 * s11 + a12 * s12;
        float E12 = a10 * s02 + a11 * s12 + a12 * s22;
        float E20 = a20 * s00 + a21 * s01 + a22 * s02;
        float E21 = a20 * s01 + a21 * s11 + a22 * s12;
        float E22 = a20 * s02 + a21 * s12 + a22 * s22;

        // innovation summaries from pre-pass
        float t0 = zc0 - G0 * ep0;
        float t1 = zc1 - G1 * ep1;
        float t2 = zc2 - G2 * ep2;
        float h0 = G0 * ep0 - 2.0f * zc0;
        float h1 = G1 * ep1 - 2.0f * zc1;
        float h2 = G2 * ep2 - 2.0f * zc2;
        float vDv = zyd + ep0 * h0 + ep1 * h1 + ep2 * h2;

        float m0 = E00 * t0 + E01 * t1 + E02 * t2;
        float m1 = E10 * t0 + E11 * t1 + E12 * t2;
        float m2 = E20 * t0 + E21 * t1 + E22 * t2;
        float quad = t0 * m0 + t1 * m1 + t2 * m2;

        // exp(ll1) = exp(Cll - 0.5*(vDv - quad)) / sqrt(det)
        float el1 = __expf(Cll - 0.5f * (vDv - quad)) * rdet;

        // J = I - diag(G) E
        float J00 = 1.f - G0 * E00, J01 = -G0 * E01, J02 = -G0 * E02;
        float J10 = -G1 * E10, J11 = 1.f - G1 * E11, J12 = -G1 * E12;
        float J20 = -G2 * E20, J21 = -G2 * E21, J22 = 1.f - G2 * E22;

        // H = P_pred[:, :3] * J
        float H00 = s00 * J00 + s01 * J10 + s02 * J20;
        float H01 = s00 * J01 + s01 * J11 + s02 * J21;
        float H02 = s00 * J02 + s01 * J12 + s02 * J22;
        float H10 = s01 * J00 + s11 * J10 + s12 * J20;
        float H11 = s01 * J01 + s11 * J11 + s12 * J21;
        float H12 = s01 * J02 + s11 * J12 + s12 * J22;
        float H20 = s02 * J00 + s12 * J10 + s22 * J20;
        float H21 = s02 * J01 + s12 * J11 + s22 * J21;
        float H22 = s02 * J02 + s12 * J12 + s22 * J22;
        float H30 = s03 * J00 + s13 * J10 + s23 * J20;
        float H31 = s03 * J01 + s13 * J11 + s23 * J21;
        float H32 = s03 * J02 + s13 * J12 + s23 * J22;

        // eta1 = eta_pred + H t
        float q10 = ep0 + H00 * t0 + H01 * t1 + H02 * t2;
        float q11 = ep1 + H10 * t0 + H11 * t1 + H12 * t2;
        float q12 = ep2 + H20 * t0 + H21 * t1 + H22 * t2;
        float q13 = ep3 + H30 * t0 + H31 * t1 + H32 * t2;

        // HG = H diag(G);  P1 = (I - K L1) P_pred   (non-Joseph; exact for optimal K)
        float HG00 = H00 * G0, HG01 = H01 * G1, HG02 = H02 * G2;
        float HG10 = H10 * G0, HG11 = H11 * G1, HG12 = H12 * G2;
        float HG20 = H20 * G0, HG21 = H21 * G1, HG22 = H22 * G2;
        float HG30 = H30 * G0, HG31 = H31 * G1, HG32 = H32 * G2;

        float P1_00 = s00 - (HG00 * s00 + HG01 * s01 + HG02 * s02);
        float P1_01 = s01 - (HG00 * s01 + HG01 * s11 + HG02 * s12);
        float P1_02 = s02 - (HG00 * s02 + HG01 * s12 + HG02 * s22);
        float P1_03 = s03 - (HG00 * s03 + HG01 * s13 + HG02 * s23);
        float P1_11 = s11 - (HG10 * s01 + HG11 * s11 + HG12 * s12);
        float P1_12 = s12 - (HG10 * s02 + HG11 * s12 + HG12 * s22);
        float P1_13 = s13 - (HG10 * s03 + HG11 * s13 + HG12 * s23);
        float P1_22 = s22 - (HG20 * s02 + HG21 * s12 + HG22 * s22);
        float P1_23 = s23 - (HG20 * s03 + HG21 * s13 + HG22 * s23);
        float P1_33 = s33 - (HG30 * s03 + HG31 * s13 + HG32 * s23);

        // ========== Regime 2: rank-1 Sherman-Morrison ==========
        float beta = 1.0f + s33 * alpha;
        float binv = rcpa(beta);
        float rbeta = rsqa(beta);

        float tau = zsu - alpha * ep3;
        float vDv2 = zyd + ep3 * (alpha * ep3 - 2.0f * zsu);
        float el2 = __expf(Cll - 0.5f * (vDv2 - s33 * tau * tau * binv)) * rbeta;

        float gk = tau * binv;
        float q20 = ep0 + s03 * gk;
        float q21 = ep1 + s13 * gk;
        float q22 = ep2 + s23 * gk;
        float q23 = ep3 + s33 * gk;

        float kap = alpha * binv;                  // non-Joseph: P2 = P - (a/b) p p^T
        float k0 = kap * s03, k1 = kap * s13, k2 = kap * s23, k3 = kap * s33;
        float P2_00 = s00 - k0 * s03;
        float P2_01 = s01 - k0 * s13;
        float P2_02 = s02 - k0 * s23;
        float P2_03 = s03 - k0 * s33;
        float P2_11 = s11 - k1 * s13;
        float P2_12 = s12 - k1 * s23;
        float P2_13 = s13 - k1 * s33;
        float P2_22 = s22 - k2 * s23;
        float P2_23 = s23 - k2 * s33;
        float P2_33 = s33 - k3 * s33;

        // ========== IMM mixing ==========
        float num1 = el1 * (pr0 * p11s);
        float num2 = el2 * (pr0 * (1.0f - p11s) + pr1);
        float marg = num1 + num2 + 1e-9f;
        llacc += __logf(marg);
        float im = rcpa(marg);
        float pa = num1 * im;
        float pb = num2 * im;

        float x0 = pa * q10 + pb * q20;
        float x1 = pa * q11 + pb * q21;
        float x2 = pa * q12 + pb * q22;
        float x3 = pa * q13 + pb * q23;

        float d10 = q10 - x0, d11 = q11 - x1, d12 = q12 - x2, d13 = q13 - x3;
        float d20 = q20 - x0, d21 = q21 - x1, d22 = q22 - x2, d23 = q23 - x3;

        p00  = pa * (P1_00 + d10 * d10) + pb * (P2_00 + d20 * d20);
        p01  = pa * (P1_01 + d10 * d11) + pb * (P2_01 + d20 * d21);
        p02  = pa * (P1_02 + d10 * d12) + pb * (P2_02 + d20 * d22);
        p03  = pa * (P1_03 + d10 * d13) + pb * (P2_03 + d20 * d23);
        p11v = pa * (P1_11 + d11 * d11) + pb * (P2_11 + d21 * d21);
        p12  = pa * (P1_12 + d11 * d12) + pb * (P2_12 + d21 * d22);
        p13  = pa * (P1_13 + d11 * d13) + pb * (P2_13 + d21 * d23);
        p22  = pa * (P1_22 + d12 * d12) + pb * (P2_22 + d22 * d22);
        p23  = pa * (P1_23 + d12 * d13) + pb * (P2_23 + d22 * d23);
        p33  = pa * (P1_33 + d13 * d13) + pb * (P2_33 + d23 * d23);

        // coalesced stores of mixing results (expanded in post-pass)
        float* S = Sb + t * 6 * NSER;
        S[0]        = pa;
        S[NSER]     = pb;
        S[2 * NSER] = x0;
        S[3 * NSER] = x1;
        S[4 * NSER] = x2;
        S[5 * NSER] = x3;

        // commit state
        e0 = x0; e1 = x1; e2 = x2; e3 = x3;
        pr0 = pa; pr1 = pb;
        zc0 = nz0; zc1 = nz1; zc2 = nz2; zsu = nz3; zyd = nz4;
    }

    g_ll[n] = llacc;
}

// ================= post-pass: S[t][6][N] -> probs[N,NT,2], y_pred[N,NT,9] =================
__global__ void postpass(const float* __restrict__ l1f,
                         const float* __restrict__ l2f,
                         float* __restrict__ out)
{
    __shared__ float sh[6][32][33];
    const int n0 = blockIdx.x * 32, t0 = blockIdx.y * 32;
    const int tx = threadIdx.x, ty = threadIdx.y;

    int tA = t0 + ty;
    if (tA < NTT) {
#pragma unroll
        for (int j = 0; j < 6; j++)
            sh[j][ty][tx] = g_S[(tA * 6 + j) * NSER + n0 + tx];
    }
    __syncthreads();

    int tt = t0 + tx;
    if (tt < NTT) {
        int n = n0 + ty;
        float pa = sh[0][tx][ty], pb = sh[1][tx][ty];
        float x0 = sh[2][tx][ty], x1 = sh[3][tx][ty];
        float x2 = sh[4][tx][ty], x3 = sh[5][tx][ty];

        size_t idx = (size_t)n * NTT + tt;
        float* probs = out + 1;
        probs[idx * 2]     = pa;
        probs[idx * 2 + 1] = pb;

        float w1 = l1f[0], w2 = l1f[1], w4 = l1f[2], w5 = l1f[3], w7 = l1f[4], w8 = l1f[5];
        float pe0 = pa * x0, pe1 = pa * x1, pe2 = pa * x2;
        float a3 = pb * x3;
        float* yo = out + 1 + (size_t)NSER * NTT * 2 + idx * 9;
        yo[0] = pe0 + a3;
        yo[1] = w1 * pe0 + l2f[0] * a3;
        yo[2] = w2 * pe0 + l2f[1] * a3;
        yo[3] = pe1 + l2f[2] * a3;
        yo[4] = w4 * pe1 + l2f[3] * a3;
        yo[5] = w5 * pe1 + l2f[4] * a3;
        yo[6] = pe2 + l2f[5] * a3;
        yo[7] = w7 * pe2 + l2f[6] * a3;
        yo[8] = w8 * pe2 + l2f[7] * a3;
    }
}

// Deterministic fixed-order reduction of per-series log-likelihoods.
__global__ void reduce_ll(float* __restrict__ out)
{
    __shared__ double sh[256];
    int t = threadIdx.x;
    double a = 0.0;
#pragma unroll
    for (int i = 0; i < 16; i++) a += (double)g_ll[t * 16 + i];
    sh[t] = a;
    __syncthreads();
#pragma unroll
    for (int s = 128; s > 0; s >>= 1) {
        if (t < s) sh[t] += sh[t + s];
        __syncthreads();
    }
    if (t == 0) out[0] = (float)(-sh[0]);
}

extern "C" void kernel_launch(void* const* d_in, const int* in_sizes, int n_in,
                              void* d_out, int out_size)
{
    (void)in_sizes; (void)n_in; (void)out_size;
    const float* y    = (const float*)d_in[0];
    const float* B1s1 = (const float*)d_in[1];
    const float* B1s2 = (const float*)d_in[2];
    const float* l1f  = (const float*)d_in[3];
    const float* l2f  = (const float*)d_in[4];
    const float* logq = (const float*)d_in[5];
    const float* logr = (const float*)d_in[6];
    const float* g0   = (const float*)d_in[7];
    const float* gc   = (const float*)d_in[8];
    float* out = (float*)d_out;

    prepass<<<(NSER * NTT) / 256, 256>>>(y, l1f, l2f, logr);
    kf_main<<<NSER / 32, 32>>>(B1s1, B1s2, l1f, l2f, logq, logr, g0, gc);
    postpass<<<dim3(NSER / 32, (NTT + 31) / 32), dim3(32, 32)>>>(l1f, l2f, out);
    reduce_ll<<<1, 256>>>(out);
}

// round 14
// speedup vs baseline: 1.3630x; 1.2638x over previous
#include <cuda_runtime.h>
#include <math.h>

#define NSER 4096
#define NTT  400
#define LOG2PI 1.8378770664093453f

// scratch for per-series log-likelihood (no allocations allowed)
__device__ float g_ll[NSER];

__device__ __forceinline__ float rcpa(float x) {
    float r; asm("rcp.approx.f32 %0,%1;" : "=f"(r) : "f"(x)); return r;
}
__device__ __forceinline__ float rsqa(float x) {
    float r; asm("rsqrt.approx.f32 %0,%1;" : "=f"(r) : "f"(x)); return r;
}

__global__ __launch_bounds__(32)
void kf_main(const float* __restrict__ y,
             const float* __restrict__ B1,
             const float* __restrict__ b2p,
             const float* __restrict__ l1f,
             const float* __restrict__ l2f,
             const float* __restrict__ logq,
             const float* __restrict__ logr,
             const float* __restrict__ g0p,
             const float* __restrict__ gcp,
             float* __restrict__ out)
{
    const int n = blockIdx.x * 32 + threadIdx.x;

    // -------- per-thread constant precompute (uniform, trivial cost) --------
    float Bm[9];
#pragma unroll
    for (int k = 0; k < 9; k++) Bm[k] = B1[k];
    const float b2 = b2p[0];
    const float w1 = l1f[0], w2 = l1f[1], w4 = l1f[2], w5 = l1f[3], w7 = l1f[4], w8 = l1f[5];
    float ws[9];
    ws[0] = 1.f; ws[1] = w1; ws[2] = w2; ws[3] = 1.f; ws[4] = w4; ws[5] = w5;
    ws[6] = 1.f; ws[7] = w7; ws[8] = w8;
    float us[9];
    us[0] = 1.f;
#pragma unroll
    for (int k = 1; k < 9; k++) us[k] = l2f[k - 1];

    float Di[9], WD[9], du[9];
    float G0 = 0.f, G1 = 0.f, G2 = 0.f;
    float logdetD = 0.f, alpha = 0.f;
#pragma unroll
    for (int o = 0; o < 9; o++) {
        float rv = expf(logr[o]);
        float Dv = rv + 1e-6f;
        float di = 1.0f / Dv;
        Di[o] = di;
        logdetD += logf(Dv);
        WD[o] = ws[o] * di;
        du[o] = us[o] * di;
        float gterm = ws[o] * ws[o] * di;
        if (o < 3)      G0 += gterm;
        else if (o < 6) G1 += gterm;
        else            G2 += gterm;
        alpha += us[o] * us[o] * di;
    }
    const float Cll = -0.5f * 9.0f * LOG2PI - 0.5f * logdetD;
    const float qv0 = expf(logq[0]), qv1 = expf(logq[1]);
    const float qv2 = expf(logq[2]), qv3 = expf(logq[3]);
    const float b2q = b2 * b2;
    const float g0 = g0p[0], gc0 = gcp[0], gc1 = gcp[1], gc2 = gcp[2];

    // -------- state --------
    float e0 = 0.f, e1 = 0.f, e2 = 0.f, e3 = 0.f;
    float p00 = 1000.f, p01 = 0.f, p02 = 0.f, p03 = 0.f;
    float p11v = 1000.f, p12 = 0.f, p13 = 0.f;
    float p22 = 1000.f, p23 = 0.f, p33 = 1000.f;
    float pr0 = 0.99f, pr1 = 0.01f;
    float llacc = 0.f;

    const float* yrow = y + (size_t)n * (NTT * 9);
    float* probs_base = out + 1;
    float* yp_base = out + 1 + (size_t)NSER * NTT * 2;

    float yv[9];
#pragma unroll
    for (int o = 0; o < 9; o++) yv[o] = yrow[o];

#pragma unroll 1
    for (int t = 0; t < NTT; t++) {
        // prefetch next timestep's observations (hide DRAM latency)
        float yn[9];
        if (t + 1 < NTT) {
            const float* yp = yrow + (t + 1) * 9;
#pragma unroll
            for (int o = 0; o < 9; o++) yn[o] = yp[o];
        }

        // observation summaries (independent of state chain — fills latency slots)
        float zc0 = WD[0] * yv[0] + WD[1] * yv[1] + WD[2] * yv[2];
        float zc1 = WD[3] * yv[3] + WD[4] * yv[4] + WD[5] * yv[5];
        float zc2 = WD[6] * yv[6] + WD[7] * yv[7] + WD[8] * yv[8];
        float zsu = du[0] * yv[0] + du[1] * yv[1] + du[2] * yv[2]
                  + du[3] * yv[3] + du[4] * yv[4] + du[5] * yv[5]
                  + du[6] * yv[6] + du[7] * yv[7] + du[8] * yv[8];
        float zyd = (Di[0] * yv[0]) * yv[0] + (Di[1] * yv[1]) * yv[1] + (Di[2] * yv[2]) * yv[2]
                  + (Di[3] * yv[3]) * yv[3] + (Di[4] * yv[4]) * yv[4] + (Di[5] * yv[5]) * yv[5]
                  + (Di[6] * yv[6]) * yv[6] + (Di[7] * yv[7]) * yv[7] + (Di[8] * yv[8]) * yv[8];

        // regime-1 stay probability
        float xg = g0 + gc0 * e0 + gc1 * e1 + gc2 * e2;
        float p11s = rcpa(1.0f + __expf(-xg));

        // ---------- predict ----------
        float ep0 = Bm[0] * e0 + Bm[1] * e1 + Bm[2] * e2;
        float ep1 = Bm[3] * e0 + Bm[4] * e1 + Bm[5] * e2;
        float ep2 = Bm[6] * e0 + Bm[7] * e1 + Bm[8] * e2;
        float ep3 = b2 * e3;

        float T00 = Bm[0] * p00 + Bm[1] * p01 + Bm[2] * p02;
        float T01 = Bm[0] * p01 + Bm[1] * p11v + Bm[2] * p12;
        float T02 = Bm[0] * p02 + Bm[1] * p12 + Bm[2] * p22;
        float T10 = Bm[3] * p00 + Bm[4] * p01 + Bm[5] * p02;
        float T11 = Bm[3] * p01 + Bm[4] * p11v + Bm[5] * p12;
        float T12 = Bm[3] * p02 + Bm[4] * p12 + Bm[5] * p22;
        float T20 = Bm[6] * p00 + Bm[7] * p01 + Bm[8] * p02;
        float T21 = Bm[6] * p01 + Bm[7] * p11v + Bm[8] * p12;
        float T22 = Bm[6] * p02 + Bm[7] * p12 + Bm[8] * p22;

        float s00 = T00 * Bm[0] + T01 * Bm[1] + T02 * Bm[2] + qv0;
        float s01 = T00 * Bm[3] + T01 * Bm[4] + T02 * Bm[5];
        float s02 = T00 * Bm[6] + T01 * Bm[7] + T02 * Bm[8];
        float s11 = T10 * Bm[3] + T11 * Bm[4] + T12 * Bm[5] + qv1;
        float s12 = T10 * Bm[6] + T11 * Bm[7] + T12 * Bm[8];
        float s22 = T20 * Bm[6] + T21 * Bm[7] + T22 * Bm[8] + qv2;
        float s03 = b2 * (Bm[0] * p03 + Bm[1] * p13 + Bm[2] * p23);
        float s13 = b2 * (Bm[3] * p03 + Bm[4] * p13 + Bm[5] * p23);
        float s23 = b2 * (Bm[6] * p03 + Bm[7] * p13 + Bm[8] * p23);
        float s33 = b2q * p33 + qv3;

        // ========== Regime 1: J = (I + diag(G) S3)^{-1} (push-through; no E) ==========
        float M00 = 1.f + G0 * s00, M01 = G0 * s01, M02 = G0 * s02;
        float M10 = G1 * s01, M11 = 1.f + G1 * s11, M12 = G1 * s12;
        float M20 = G2 * s02, M21 = G2 * s12, M22 = 1.f + G2 * s22;

        float a00 = M11 * M22 - M12 * M21;
        float a01 = M02 * M21 - M01 * M22;
        float a02 = M01 * M12 - M02 * M11;
        float a10 = M12 * M20 - M10 * M22;
        float a11 = M00 * M22 - M02 * M20;
        float a12 = M02 * M10 - M00 * M12;
        float a20 = M10 * M21 - M11 * M20;
        float a21 = M01 * M20 - M00 * M21;
        float a22 = M00 * M11 - M01 * M10;
        float det = M00 * a00 + M01 * a10 + M02 * a20;   // = det(F1)/det(D)
        float idet = rcpa(det);
        float rdet = rsqa(det);

        float J00 = a00 * idet, J01 = a01 * idet, J02 = a02 * idet;
        float J10 = a10 * idet, J11 = a11 * idet, J12 = a12 * idet;
        float J20 = a20 * idet, J21 = a21 * idet, J22 = a22 * idet;

        // innovation summaries
        float t0 = zc0 - G0 * ep0;
        float t1 = zc1 - G1 * ep1;
        float t2 = zc2 - G2 * ep2;
        float h0 = G0 * ep0 - 2.0f * zc0;
        float h1 = G1 * ep1 - 2.0f * zc1;
        float h2 = G2 * ep2 - 2.0f * zc2;
        float vDv = zyd + ep0 * h0 + ep1 * h1 + ep2 * h2;

        // quad = t^T (I+S3 G)^{-1} S3 t = (S3 t) . (J t)
        float jt0 = J00 * t0 + J01 * t1 + J02 * t2;
        float jt1 = J10 * t0 + J11 * t1 + J12 * t2;
        float jt2 = J20 * t0 + J21 * t1 + J22 * t2;
        float st0 = s00 * t0 + s01 * t1 + s02 * t2;
        float st1 = s01 * t0 + s11 * t1 + s12 * t2;
        float st2 = s02 * t0 + s12 * t1 + s22 * t2;
        float quad = st0 * jt0 + st1 * jt1 + st2 * jt2;

        // exp(ll1) = exp(Cll + 0.5*(quad - vDv)) / sqrt(det-ratio)
        float el1 = __expf(Cll + 0.5f * (quad - vDv)) * rdet;

        // eta1 = eta_pred + C (J t)   (C = P_pred[:, :3])
        float q10 = ep0 + s00 * jt0 + s01 * jt1 + s02 * jt2;
        float q11 = ep1 + s01 * jt0 + s11 * jt1 + s12 * jt2;
        float q12 = ep2 + s02 * jt0 + s12 * jt1 + s22 * jt2;
        float q13 = ep3 + s03 * jt0 + s13 * jt1 + s23 * jt2;

        // H = C J ; HG = H diag(G) ; P1 = P_pred - HG C^T  (non-Joseph, exact)
        float H00 = s00 * J00 + s01 * J10 + s02 * J20;
        float H01 = s00 * J01 + s01 * J11 + s02 * J21;
        float H02 = s00 * J02 + s01 * J12 + s02 * J22;
        float H10 = s01 * J00 + s11 * J10 + s12 * J20;
        float H11 = s01 * J01 + s11 * J11 + s12 * J21;
        float H12 = s01 * J02 + s11 * J12 + s12 * J22;
        float H20 = s02 * J00 + s12 * J10 + s22 * J20;
        float H21 = s02 * J01 + s12 * J11 + s22 * J21;
        float H22 = s02 * J02 + s12 * J12 + s22 * J22;
        float H30 = s03 * J00 + s13 * J10 + s23 * J20;
        float H31 = s03 * J01 + s13 * J11 + s23 * J21;
        float H32 = s03 * J02 + s13 * J12 + s23 * J22;

        float HG00 = H00 * G0, HG01 = H01 * G1, HG02 = H02 * G2;
        float HG10 = H10 * G0, HG11 = H11 * G1, HG12 = H12 * G2;
        float HG20 = H20 * G0, HG21 = H21 * G1, HG22 = H22 * G2;
        float HG30 = H30 * G0, HG31 = H31 * G1, HG32 = H32 * G2;

        float P1_00 = s00 - (HG00 * s00 + HG01 * s01 + HG02 * s02);
        float P1_01 = s01 - (HG00 * s01 + HG01 * s11 + HG02 * s12);
        float P1_02 = s02 - (HG00 * s02 + HG01 * s12 + HG02 * s22);
        float P1_03 = s03 - (HG00 * s03 + HG01 * s13 + HG02 * s23);
        float P1_11 = s11 - (HG10 * s01 + HG11 * s11 + HG12 * s12);
        float P1_12 = s12 - (HG10 * s02 + HG11 * s12 + HG12 * s22);
        float P1_13 = s13 - (HG10 * s03 + HG11 * s13 + HG12 * s23);
        float P1_22 = s22 - (HG20 * s02 + HG21 * s12 + HG22 * s22);
        float P1_23 = s23 - (HG20 * s03 + HG21 * s13 + HG22 * s23);
        float P1_33 = s33 - (HG30 * s03 + HG31 * s13 + HG32 * s23);

        // ========== Regime 2: rank-1 Sherman-Morrison ==========
        float beta = 1.0f + s33 * alpha;
        float binv = rcpa(beta);
        float rbeta = rsqa(beta);

        float tau = zsu - alpha * ep3;
        float vDv2 = zyd + ep3 * (alpha * ep3 - 2.0f * zsu);
        float el2 = __expf(Cll - 0.5f * (vDv2 - s33 * tau * tau * binv)) * rbeta;

        float gk = tau * binv;
        float q20 = ep0 + s03 * gk;
        float q21 = ep1 + s13 * gk;
        float q22 = ep2 + s23 * gk;
        float q23 = ep3 + s33 * gk;

        float kap = alpha * binv;                  // P2 = P_pred - (a/b) p p^T
        float k0 = kap * s03, k1 = kap * s13, k2 = kap * s23, k3 = kap * s33;
        float P2_00 = s00 - k0 * s03;
        float P2_01 = s01 - k0 * s13;
        float P2_02 = s02 - k0 * s23;
        float P2_03 = s03 - k0 * s33;
        float P2_11 = s11 - k1 * s13;
        float P2_12 = s12 - k1 * s23;
        float P2_13 = s13 - k1 * s33;
        float P2_22 = s22 - k2 * s23;
        float P2_23 = s23 - k2 * s33;
        float P2_33 = s33 - k3 * s33;

        // ========== IMM mixing ==========
        float num1 = el1 * (pr0 * p11s);
        float num2 = el2 * (pr0 * (1.0f - p11s) + pr1);
        float marg = num1 + num2 + 1e-9f;
        llacc += __logf(marg);
        float im = rcpa(marg);
        float pa = num1 * im;
        float pb = num2 * im;

        float x0 = pa * q10 + pb * q20;
        float x1 = pa * q11 + pb * q21;
        float x2 = pa * q12 + pb * q22;
        float x3 = pa * q13 + pb * q23;

        float d10 = q10 - x0, d11 = q11 - x1, d12 = q12 - x2, d13 = q13 - x3;
        float d20 = q20 - x0, d21 = q21 - x1, d22 = q22 - x2, d23 = q23 - x3;

        p00  = pa * (P1_00 + d10 * d10) + pb * (P2_00 + d20 * d20);
        p01  = pa * (P1_01 + d10 * d11) + pb * (P2_01 + d20 * d21);
        p02  = pa * (P1_02 + d10 * d12) + pb * (P2_02 + d20 * d22);
        p03  = pa * (P1_03 + d10 * d13) + pb * (P2_03 + d20 * d23);
        p11v = pa * (P1_11 + d11 * d11) + pb * (P2_11 + d21 * d21);
        p12  = pa * (P1_12 + d11 * d12) + pb * (P2_12 + d21 * d22);
        p13  = pa * (P1_13 + d11 * d13) + pb * (P2_13 + d21 * d23);
        p22  = pa * (P1_22 + d12 * d12) + pb * (P2_22 + d22 * d22);
        p23  = pa * (P1_23 + d12 * d13) + pb * (P2_23 + d22 * d23);
        p33  = pa * (P1_33 + d13 * d13) + pb * (P2_33 + d23 * d23);

        // ------------- outputs (inline; latency hidden, proven in R5) -------------
        size_t idx = (size_t)n * NTT + t;
        probs_base[idx * 2]     = pa;
        probs_base[idx * 2 + 1] = pb;

        float* yo = yp_base + idx * 9;
        float pe0 = pa * x0, pe1 = pa * x1, pe2 = pa * x2;
        float a3 = pb * x3;
        yo[0] = pe0 + a3;
        yo[1] = w1 * pe0 + us[1] * a3;
        yo[2] = w2 * pe0 + us[2] * a3;
        yo[3] = pe1 + us[3] * a3;
        yo[4] = w4 * pe1 + us[4] * a3;
        yo[5] = w5 * pe1 + us[5] * a3;
        yo[6] = pe2 + us[6] * a3;
        yo[7] = w7 * pe2 + us[7] * a3;
        yo[8] = w8 * pe2 + us[8] * a3;

        // commit state
        e0 = x0; e1 = x1; e2 = x2; e3 = x3;
        pr0 = pa; pr1 = pb;
#pragma unroll
        for (int o = 0; o < 9; o++) yv[o] = yn[o];
    }

    g_ll[n] = llacc;
}

// Deterministic fixed-order reduction of per-series log-likelihoods.
__global__ void reduce_ll(float* __restrict__ out)
{
    __shared__ double sh[256];
    int t = threadIdx.x;
    double a = 0.0;
#pragma unroll
    for (int i = 0; i < 16; i++) a += (double)g_ll[t * 16 + i];
    sh[t] = a;
    __syncthreads();
#pragma unroll
    for (int s = 128; s > 0; s >>= 1) {
        if (t < s) sh[t] += sh[t + s];
        __syncthreads();
    }
    if (t == 0) out[0] = (float)(-sh[0]);
}

extern "C" void kernel_launch(void* const* d_in, const int* in_sizes, int n_in,
                              void* d_out, int out_size)
{
    (void)in_sizes; (void)n_in; (void)out_size;
    const float* y    = (const float*)d_in[0];
    const float* B1s1 = (const float*)d_in[1];
    const float* B1s2 = (const float*)d_in[2];
    const float* l1f  = (const float*)d_in[3];
    const float* l2f  = (const float*)d_in[4];
    const float* logq = (const float*)d_in[5];
    const float* logr = (const float*)d_in[6];
    const float* g0   = (const float*)d_in[7];
    const float* gc   = (const float*)d_in[8];
    float* out = (float*)d_out;

    kf_main<<<NSER / 32, 32>>>(y, B1s1, B1s2, l1f, l2f, logq, logr, g0, gc, out);
    reduce_ll<<<1, 256>>>(out);
}

// round 16
// speedup vs baseline: 1.3981x; 1.0257x over previous
#include <cuda_runtime.h>
#include <math.h>

#define NSER 4096
#define NTT  400
#define LOG2PI 1.8378770664093453f

// scratch for per-series log-likelihood (no allocations allowed)
__device__ float g_ll[NSER];

__device__ __forceinline__ float rcpa(float x) {
    float r; asm("rcp.approx.f32 %0,%1;" : "=f"(r) : "f"(x)); return r;
}
__device__ __forceinline__ float rsqa(float x) {
    float r; asm("rsqrt.approx.f32 %0,%1;" : "=f"(r) : "f"(x)); return r;
}

__global__ __launch_bounds__(32, 1)
void kf_main(const float* __restrict__ y,
             const float* __restrict__ B1,
             const float* __restrict__ b2p,
             const float* __restrict__ l1f,
             const float* __restrict__ l2f,
             const float* __restrict__ logq,
             const float* __restrict__ logr,
             const float* __restrict__ g0p,
             const float* __restrict__ gcp,
             float* __restrict__ out)
{
    const int n = blockIdx.x * 32 + threadIdx.x;

    // -------- per-thread constant precompute (uniform, trivial cost) --------
    float Bm[9];
#pragma unroll
    for (int k = 0; k < 9; k++) Bm[k] = B1[k];
    const float b2 = b2p[0];
    const float w1 = l1f[0], w2 = l1f[1], w4 = l1f[2], w5 = l1f[3], w7 = l1f[4], w8 = l1f[5];
    float ws[9];
    ws[0] = 1.f; ws[1] = w1; ws[2] = w2; ws[3] = 1.f; ws[4] = w4; ws[5] = w5;
    ws[6] = 1.f; ws[7] = w7; ws[8] = w8;
    float us[9];
    us[0] = 1.f;
#pragma unroll
    for (int k = 1; k < 9; k++) us[k] = l2f[k - 1];

    float Di[9], WD[9], du[9];
    float G0 = 0.f, G1 = 0.f, G2 = 0.f;
    float logdetD = 0.f, alpha = 0.f;
#pragma unroll
    for (int o = 0; o < 9; o++) {
        float rv = expf(logr[o]);
        float Dv = rv + 1e-6f;
        float di = 1.0f / Dv;
        Di[o] = di;
        logdetD += logf(Dv);
        WD[o] = ws[o] * di;
        du[o] = us[o] * di;
        float gterm = ws[o] * ws[o] * di;
        if (o < 3)      G0 += gterm;
        else if (o < 6) G1 += gterm;
        else            G2 += gterm;
        alpha += us[o] * us[o] * di;
    }
    const float Cll = -0.5f * 9.0f * LOG2PI - 0.5f * logdetD;
    const float qv0 = expf(logq[0]), qv1 = expf(logq[1]);
    const float qv2 = expf(logq[2]), qv3 = expf(logq[3]);
    const float b2q = b2 * b2;
    const float g0 = g0p[0], gc0 = gcp[0], gc1 = gcp[1], gc2 = gcp[2];

    // -------- state --------
    float e0 = 0.f, e1 = 0.f, e2 = 0.f, e3 = 0.f;
    float p00 = 1000.f, p01 = 0.f, p02 = 0.f, p03 = 0.f;
    float p11v = 1000.f, p12 = 0.f, p13 = 0.f;
    float p22 = 1000.f, p23 = 0.f, p33 = 1000.f;
    float pr0 = 0.99f, pr1 = 0.01f;    // explicit carry: pr0+pr1 may drift below 1 (EPS)
    float llacc = 0.f;

    const float* yrow = y + (size_t)n * (NTT * 9);
    float* probs_base = out + 1;
    float* yp_base = out + 1 + (size_t)NSER * NTT * 2;

    float yv[9];
#pragma unroll
    for (int o = 0; o < 9; o++) yv[o] = yrow[o];

#pragma unroll 1
    for (int t = 0; t < NTT; t++) {
        // prefetch next timestep's observations (hide DRAM latency)
        float yn[9];
        if (t + 1 < NTT) {
            const float* yp = yrow + (t + 1) * 9;
#pragma unroll
            for (int o = 0; o < 9; o++) yn[o] = yp[o];
        }

        // observation summaries (independent of state chain — fills latency slots)
        float zc0 = WD[0] * yv[0] + WD[1] * yv[1] + WD[2] * yv[2];
        float zc1 = WD[3] * yv[3] + WD[4] * yv[4] + WD[5] * yv[5];
        float zc2 = WD[6] * yv[6] + WD[7] * yv[7] + WD[8] * yv[8];
        float zsu = du[0] * yv[0] + du[1] * yv[1] + du[2] * yv[2]
                  + du[3] * yv[3] + du[4] * yv[4] + du[5] * yv[5]
                  + du[6] * yv[6] + du[7] * yv[7] + du[8] * yv[8];
        float zyd = (Di[0] * yv[0]) * yv[0] + (Di[1] * yv[1]) * yv[1] + (Di[2] * yv[2]) * yv[2]
                  + (Di[3] * yv[3]) * yv[3] + (Di[4] * yv[4]) * yv[4] + (Di[5] * yv[5]) * yv[5]
                  + (Di[6] * yv[6]) * yv[6] + (Di[7] * yv[7]) * yv[7] + (Di[8] * yv[8]) * yv[8];

        // regime-1 stay probability
        float xg = g0 + gc0 * e0 + gc1 * e1 + gc2 * e2;
        float p11s = rcpa(1.0f + __expf(-xg));

        // ---------- predict ----------
        float ep0 = Bm[0] * e0 + Bm[1] * e1 + Bm[2] * e2;
        float ep1 = Bm[3] * e0 + Bm[4] * e1 + Bm[5] * e2;
        float ep2 = Bm[6] * e0 + Bm[7] * e1 + Bm[8] * e2;
        float ep3 = b2 * e3;

        float T00 = Bm[0] * p00 + Bm[1] * p01 + Bm[2] * p02;
        float T01 = Bm[0] * p01 + Bm[1] * p11v + Bm[2] * p12;
        float T02 = Bm[0] * p02 + Bm[1] * p12 + Bm[2] * p22;
        float T10 = Bm[3] * p00 + Bm[4] * p01 + Bm[5] * p02;
        float T11 = Bm[3] * p01 + Bm[4] * p11v + Bm[5] * p12;
        float T12 = Bm[3] * p02 + Bm[4] * p12 + Bm[5] * p22;
        float T20 = Bm[6] * p00 + Bm[7] * p01 + Bm[8] * p02;
        float T21 = Bm[6] * p01 + Bm[7] * p11v + Bm[8] * p12;
        float T22 = Bm[6] * p02 + Bm[7] * p12 + Bm[8] * p22;

        float s00 = T00 * Bm[0] + T01 * Bm[1] + T02 * Bm[2] + qv0;
        float s01 = T00 * Bm[3] + T01 * Bm[4] + T02 * Bm[5];
        float s02 = T00 * Bm[6] + T01 * Bm[7] + T02 * Bm[8];
        float s11 = T10 * Bm[3] + T11 * Bm[4] + T12 * Bm[5] + qv1;
        float s12 = T10 * Bm[6] + T11 * Bm[7] + T12 * Bm[8];
        float s22 = T20 * Bm[6] + T21 * Bm[7] + T22 * Bm[8] + qv2;
        float s03 = b2 * (Bm[0] * p03 + Bm[1] * p13 + Bm[2] * p23);
        float s13 = b2 * (Bm[3] * p03 + Bm[4] * p13 + Bm[5] * p23);
        float s23 = b2 * (Bm[6] * p03 + Bm[7] * p13 + Bm[8] * p23);
        float s33 = b2q * p33 + qv3;

        // ========== Regime 1: M = I + diag(G) S3; adjugate kept UNNORMALIZED ==========
        float M00 = 1.f + G0 * s00, M01 = G0 * s01, M02 = G0 * s02;
        float M10 = G1 * s01, M11 = 1.f + G1 * s11, M12 = G1 * s12;
        float M20 = G2 * s02, M21 = G2 * s12, M22 = 1.f + G2 * s22;

        float a00 = M11 * M22 - M12 * M21;
        float a01 = M02 * M21 - M01 * M22;
        float a02 = M01 * M12 - M02 * M11;
        float a10 = M12 * M20 - M10 * M22;
        float a11 = M00 * M22 - M02 * M20;
        float a12 = M02 * M10 - M00 * M12;
        float a20 = M10 * M21 - M11 * M20;
        float a21 = M01 * M20 - M00 * M21;
        float a22 = M00 * M11 - M01 * M10;
        float det = M00 * a00 + M01 * a10 + M02 * a20;   // = det(F1)/det(D)
        float idet = rcpa(det);
        float rdet = rsqa(det);
        float nidet = -idet;

        // innovation summaries
        float t0 = zc0 - G0 * ep0;
        float t1 = zc1 - G1 * ep1;
        float t2 = zc2 - G2 * ep2;
        float h0 = G0 * ep0 - 2.0f * zc0;
        float h1 = G1 * ep1 - 2.0f * zc1;
        float h2 = G2 * ep2 - 2.0f * zc2;
        float vDv = zyd + ep0 * h0 + ep1 * h1 + ep2 * h2;

        // jt_u = adj * t (unnormalized);  quad = idet * (S3 t . jt_u)
        float jt0 = a00 * t0 + a01 * t1 + a02 * t2;
        float jt1 = a10 * t0 + a11 * t1 + a12 * t2;
        float jt2 = a20 * t0 + a21 * t1 + a22 * t2;
        float st0 = s00 * t0 + s01 * t1 + s02 * t2;
        float st1 = s01 * t0 + s11 * t1 + s12 * t2;
        float st2 = s02 * t0 + s12 * t1 + s22 * t2;
        float quad = idet * (st0 * jt0 + st1 * jt1 + st2 * jt2);

        float el1 = __expf(Cll + 0.5f * (quad - vDv)) * rdet;

        // eta1 = ep + idet * C (adj t)   (C = P_pred[:, :3])
        float q10 = ep0 + idet * (s00 * jt0 + s01 * jt1 + s02 * jt2);
        float q11 = ep1 + idet * (s01 * jt0 + s11 * jt1 + s12 * jt2);
        float q12 = ep2 + idet * (s02 * jt0 + s12 * jt1 + s22 * jt2);
        float q13 = ep3 + idet * (s03 * jt0 + s13 * jt1 + s23 * jt2);

        // W = C * adj (4x3, unnormalized);  V = W diag(G);  P1 = s - idet * V C^T
        float W00 = s00 * a00 + s01 * a10 + s02 * a20;
        float W01 = s00 * a01 + s01 * a11 + s02 * a21;
        float W02 = s00 * a02 + s01 * a12 + s02 * a22;
        float W10 = s01 * a00 + s11 * a10 + s12 * a20;
        float W11 = s01 * a01 + s11 * a11 + s12 * a21;
        float W12 = s01 * a02 + s11 * a12 + s12 * a22;
        float W20 = s02 * a00 + s12 * a10 + s22 * a20;
        float W21 = s02 * a01 + s12 * a11 + s22 * a21;
        float W22 = s02 * a02 + s12 * a12 + s22 * a22;
        float W30 = s03 * a00 + s13 * a10 + s23 * a20;
        float W31 = s03 * a01 + s13 * a11 + s23 * a21;
        float W32 = s03 * a02 + s13 * a12 + s23 * a22;

        float V00 = W00 * G0, V01 = W01 * G1, V02 = W02 * G2;
        float V10 = W10 * G0, V11 = W11 * G1, V12 = W12 * G2;
        float V20 = W20 * G0, V21 = W21 * G1, V22 = W22 * G2;
        float V30 = W30 * G0, V31 = W31 * G1, V32 = W32 * G2;

        float P1_00 = s00 + nidet * (V00 * s00 + V01 * s01 + V02 * s02);
        float P1_01 = s01 + nidet * (V00 * s01 + V01 * s11 + V02 * s12);
        float P1_02 = s02 + nidet * (V00 * s02 + V01 * s12 + V02 * s22);
        float P1_03 = s03 + nidet * (V00 * s03 + V01 * s13 + V02 * s23);
        float P1_11 = s11 + nidet * (V10 * s01 + V11 * s11 + V12 * s12);
        float P1_12 = s12 + nidet * (V10 * s02 + V11 * s12 + V12 * s22);
        float P1_13 = s13 + nidet * (V10 * s03 + V11 * s13 + V12 * s23);
        float P1_22 = s22 + nidet * (V20 * s02 + V21 * s12 + V22 * s22);
        float P1_23 = s23 + nidet * (V20 * s03 + V21 * s13 + V22 * s23);
        float P1_33 = s33 + nidet * (V30 * s03 + V31 * s13 + V32 * s23);

        // ========== Regime 2: rank-1 Sherman-Morrison ==========
        float beta = 1.0f + s33 * alpha;
        float binv = rcpa(beta);
        float rbeta = rsqa(beta);

        float tau = zsu - alpha * ep3;
        float vDv2 = zyd + ep3 * (alpha * ep3 - 2.0f * zsu);
        float el2 = __expf(Cll - 0.5f * (vDv2 - s33 * tau * tau * binv)) * rbeta;

        float gk = tau * binv;
        float q20 = ep0 + s03 * gk;
        float q21 = ep1 + s13 * gk;
        float q22 = ep2 + s23 * gk;
        float q23 = ep3 + s33 * gk;

        float kap = alpha * binv;                  // P2 = P_pred - (a/b) p p^T
        float k0 = kap * s03, k1 = kap * s13, k2 = kap * s23, k3 = kap * s33;
        float P2_00 = s00 - k0 * s03;
        float P2_01 = s01 - k0 * s13;
        float P2_02 = s02 - k0 * s23;
        float P2_03 = s03 - k0 * s33;
        float P2_11 = s11 - k1 * s13;
        float P2_12 = s12 - k1 * s23;
        float P2_13 = s13 - k1 * s33;
        float P2_22 = s22 - k2 * s23;
        float P2_23 = s23 - k2 * s33;
        float P2_33 = s33 - k3 * s33;

        // ========== IMM mixing (EXACT reference semantics: EPS makes pa+pb < 1) ==========
        float num1 = el1 * (pr0 * p11s);
        float num2 = el2 * (pr0 * (1.0f - p11s) + pr1);
        float marg = num1 + num2 + 1e-9f;
        llacc += __logf(marg);
        float im = rcpa(marg);
        float pa = num1 * im;
        float pb = num2 * im;

        float x0 = pa * q10 + pb * q20;
        float x1 = pa * q11 + pb * q21;
        float x2 = pa * q12 + pb * q22;
        float x3 = pa * q13 + pb * q23;

        float d10 = q10 - x0, d11 = q11 - x1, d12 = q12 - x2, d13 = q13 - x3;
        float d20 = q20 - x0, d21 = q21 - x1, d22 = q22 - x2, d23 = q23 - x3;

        p00  = pa * (P1_00 + d10 * d10) + pb * (P2_00 + d20 * d20);
        p01  = pa * (P1_01 + d10 * d11) + pb * (P2_01 + d20 * d21);
        p02  = pa * (P1_02 + d10 * d12) + pb * (P2_02 + d20 * d22);
        p03  = pa * (P1_03 + d10 * d13) + pb * (P2_03 + d20 * d23);
        p11v = pa * (P1_11 + d11 * d11) + pb * (P2_11 + d21 * d21);
        p12  = pa * (P1_12 + d11 * d12) + pb * (P2_12 + d21 * d22);
        p13  = pa * (P1_13 + d11 * d13) + pb * (P2_13 + d21 * d23);
        p22  = pa * (P1_22 + d12 * d12) + pb * (P2_22 + d22 * d22);
        p23  = pa * (P1_23 + d12 * d13) + pb * (P2_23 + d22 * d23);
        p33  = pa * (P1_33 + d13 * d13) + pb * (P2_33 + d23 * d23);

        // ------------- outputs (inline; latency hidden) -------------
        size_t idx = (size_t)n * NTT + t;
        probs_base[idx * 2]     = pa;
        probs_base[idx * 2 + 1] = pb;

        float* yo = yp_base + idx * 9;
        float pe0 = pa * x0, pe1 = pa * x1, pe2 = pa * x2;
        float a3 = pb * x3;
        yo[0] = pe0 + a3;
        yo[1] = w1 * pe0 + us[1] * a3;
        yo[2] = w2 * pe0 + us[2] * a3;
        yo[3] = pe1 + us[3] * a3;
        yo[4] = w4 * pe1 + us[4] * a3;
        yo[5] = w5 * pe1 + us[5] * a3;
        yo[6] = pe2 + us[6] * a3;
        yo[7] = w7 * pe2 + us[7] * a3;
        yo[8] = w8 * pe2 + us[8] * a3;

        // commit state
        e0 = x0; e1 = x1; e2 = x2; e3 = x3;
        pr0 = pa; pr1 = pb;
#pragma unroll
        for (int o = 0; o < 9; o++) yv[o] = yn[o];
    }

    g_ll[n] = llacc;
}

// Deterministic fixed-order reduction of per-series log-likelihoods.
__global__ void reduce_ll(float* __restrict__ out)
{
    __shared__ double sh[256];
    int t = threadIdx.x;
    double a = 0.0;
#pragma unroll
    for (int i = 0; i < 16; i++) a += (double)g_ll[t * 16 + i];
    sh[t] = a;
    __syncthreads();
#pragma unroll
    for (int s = 128; s > 0; s >>= 1) {
        if (t < s) sh[t] += sh[t + s];
        __syncthreads();
    }
    if (t == 0) out[0] = (float)(-sh[0]);
}

extern "C" void kernel_launch(void* const* d_in, const int* in_sizes, int n_in,
                              void* d_out, int out_size)
{
    (void)in_sizes; (void)n_in; (void)out_size;
    const float* y    = (const float*)d_in[0];
    const float* B1s1 = (const float*)d_in[1];
    const float* B1s2 = (const float*)d_in[2];
    const float* l1f  = (const float*)d_in[3];
    const float* l2f  = (const float*)d_in[4];
    const float* logq = (const float*)d_in[5];
    const float* logr = (const float*)d_in[6];
    const float* g0   = (const float*)d_in[7];
    const float* gc   = (const float*)d_in[8];
    float* out = (float*)d_out;

    kf_main<<<NSER / 32, 32>>>(y, B1s1, B1s2, l1f, l2f, logq, logr, g0, gc, out);
    reduce_ll<<<1, 256>>>(out);
}

// round 17
// speedup vs baseline: 1.4000x; 1.0013x over previous
#include <cuda_runtime.h>
#include <math.h>

#define NSER 4096
#define NTT  400
#define LOG2PI 1.8378770664093453f

// scratch for per-series log-likelihood (no allocations allowed)
__device__ float g_ll[NSER];

__device__ __forceinline__ float rcpa(float x) {
    float r; asm("rcp.approx.f32 %0,%1;" : "=f"(r) : "f"(x)); return r;
}
__device__ __forceinline__ float rsqa(float x) {
    float r; asm("rsqrt.approx.f32 %0,%1;" : "=f"(r) : "f"(x)); return r;
}

__global__ __launch_bounds__(32, 1)
void kf_main(const float* __restrict__ y,
             const float* __restrict__ B1,
             const float* __restrict__ b2p,
             const float* __restrict__ l1f,
             const float* __restrict__ l2f,
             const float* __restrict__ logq,
             const float* __restrict__ logr,
             const float* __restrict__ g0p,
             const float* __restrict__ gcp,
             float* __restrict__ out)
{
    const int n = blockIdx.x * 32 + threadIdx.x;

    // -------- per-thread constant precompute (uniform, trivial cost) --------
    float Bm[9];
#pragma unroll
    for (int k = 0; k < 9; k++) Bm[k] = B1[k];
    const float b2 = b2p[0];
    const float w1 = l1f[0], w2 = l1f[1], w4 = l1f[2], w5 = l1f[3], w7 = l1f[4], w8 = l1f[5];
    float ws[9];
    ws[0] = 1.f; ws[1] = w1; ws[2] = w2; ws[3] = 1.f; ws[4] = w4; ws[5] = w5;
    ws[6] = 1.f; ws[7] = w7; ws[8] = w8;
    float us[9];
    us[0] = 1.f;
#pragma unroll
    for (int k = 1; k < 9; k++) us[k] = l2f[k - 1];

    float Di[9], WD[9], du[9];
    float G0 = 0.f, G1 = 0.f, G2 = 0.f;
    float logdetD = 0.f, alpha = 0.f;
#pragma unroll
    for (int o = 0; o < 9; o++) {
        float rv = expf(logr[o]);
        float Dv = rv + 1e-6f;
        float di = 1.0f / Dv;
        Di[o] = di;
        logdetD += logf(Dv);
        WD[o] = ws[o] * di;
        du[o] = us[o] * di;
        float gterm = ws[o] * ws[o] * di;
        if (o < 3)      G0 += gterm;
        else if (o < 6) G1 += gterm;
        else            G2 += gterm;
        alpha += us[o] * us[o] * di;
    }
    const float Cll = -0.5f * 9.0f * LOG2PI - 0.5f * logdetD;
    const float qv0 = expf(logq[0]), qv1 = expf(logq[1]);
    const float qv2 = expf(logq[2]), qv3 = expf(logq[3]);
    const float b2q = b2 * b2;
    const float g0 = g0p[0], gc0 = gcp[0], gc1 = gcp[1], gc2 = gcp[2];

    // -------- state --------
    float e0 = 0.f, e1 = 0.f, e2 = 0.f, e3 = 0.f;
    float p00 = 1000.f, p01 = 0.f, p02 = 0.f, p03 = 0.f;
    float p11v = 1000.f, p12 = 0.f, p13 = 0.f;
    float p22 = 1000.f, p23 = 0.f, p33 = 1000.f;
    float pr0 = 0.99f, pr1 = 0.01f;    // explicit carry: pr0+pr1 may drift below 1 (EPS)
    float llacc = 0.f;

    const float* yrow = y + (size_t)n * (NTT * 9);
    float* probs_base = out + 1;
    float* yp_base = out + 1 + (size_t)NSER * NTT * 2;

    float yv[9];
#pragma unroll
    for (int o = 0; o < 9; o++) yv[o] = yrow[o];

#pragma unroll 1
    for (int t = 0; t < NTT; t++) {
        // prefetch next timestep's observations (hide DRAM latency)
        float yn[9];
        if (t + 1 < NTT) {
            const float* yp = yrow + (t + 1) * 9;
#pragma unroll
            for (int o = 0; o < 9; o++) yn[o] = yp[o];
        }

        // observation summaries (independent of state chain — fills latency slots)
        float zc0 = WD[0] * yv[0] + WD[1] * yv[1] + WD[2] * yv[2];
        float zc1 = WD[3] * yv[3] + WD[4] * yv[4] + WD[5] * yv[5];
        float zc2 = WD[6] * yv[6] + WD[7] * yv[7] + WD[8] * yv[8];
        float zsu = du[0] * yv[0] + du[1] * yv[1] + du[2] * yv[2]
                  + du[3] * yv[3] + du[4] * yv[4] + du[5] * yv[5]
                  + du[6] * yv[6] + du[7] * yv[7] + du[8] * yv[8];
        float zyd = (Di[0] * yv[0]) * yv[0] + (Di[1] * yv[1]) * yv[1] + (Di[2] * yv[2]) * yv[2]
                  + (Di[3] * yv[3]) * yv[3] + (Di[4] * yv[4]) * yv[4] + (Di[5] * yv[5]) * yv[5]
                  + (Di[6] * yv[6]) * yv[6] + (Di[7] * yv[7]) * yv[7] + (Di[8] * yv[8]) * yv[8];

        // regime-1 stay probability
        float xg = g0 + gc0 * e0 + gc1 * e1 + gc2 * e2;
        float p11s = rcpa(1.0f + __expf(-xg));

        // ---------- predict ----------
        float ep0 = Bm[0] * e0 + Bm[1] * e1 + Bm[2] * e2;
        float ep1 = Bm[3] * e0 + Bm[4] * e1 + Bm[5] * e2;
        float ep2 = Bm[6] * e0 + Bm[7] * e1 + Bm[8] * e2;
        float ep3 = b2 * e3;

        float T00 = Bm[0] * p00 + Bm[1] * p01 + Bm[2] * p02;
        float T01 = Bm[0] * p01 + Bm[1] * p11v + Bm[2] * p12;
        float T02 = Bm[0] * p02 + Bm[1] * p12 + Bm[2] * p22;
        float T10 = Bm[3] * p00 + Bm[4] * p01 + Bm[5] * p02;
        float T11 = Bm[3] * p01 + Bm[4] * p11v + Bm[5] * p12;
        float T12 = Bm[3] * p02 + Bm[4] * p12 + Bm[5] * p22;
        float T20 = Bm[6] * p00 + Bm[7] * p01 + Bm[8] * p02;
        float T21 = Bm[6] * p01 + Bm[7] * p11v + Bm[8] * p12;
        float T22 = Bm[6] * p02 + Bm[7] * p12 + Bm[8] * p22;

        float s00 = T00 * Bm[0] + T01 * Bm[1] + T02 * Bm[2] + qv0;
        float s01 = T00 * Bm[3] + T01 * Bm[4] + T02 * Bm[5];
        float s02 = T00 * Bm[6] + T01 * Bm[7] + T02 * Bm[8];
        float s11 = T10 * Bm[3] + T11 * Bm[4] + T12 * Bm[5] + qv1;
        float s12 = T10 * Bm[6] + T11 * Bm[7] + T12 * Bm[8];
        float s22 = T20 * Bm[6] + T21 * Bm[7] + T22 * Bm[8] + qv2;
        float s03 = b2 * (Bm[0] * p03 + Bm[1] * p13 + Bm[2] * p23);
        float s13 = b2 * (Bm[3] * p03 + Bm[4] * p13 + Bm[5] * p23);
        float s23 = b2 * (Bm[6] * p03 + Bm[7] * p13 + Bm[8] * p23);
        float s33 = b2q * p33 + qv3;

        // ========== Regime 1: M = I + diag(G) S3; adjugate kept UNNORMALIZED ==========
        float M00 = 1.f + G0 * s00, M01 = G0 * s01, M02 = G0 * s02;
        float M10 = G1 * s01, M11 = 1.f + G1 * s11, M12 = G1 * s12;
        float M20 = G2 * s02, M21 = G2 * s12, M22 = 1.f + G2 * s22;

        float a00 = M11 * M22 - M12 * M21;
        float a01 = M02 * M21 - M01 * M22;
        float a02 = M01 * M12 - M02 * M11;
        float a10 = M12 * M20 - M10 * M22;
        float a11 = M00 * M22 - M02 * M20;
        float a12 = M02 * M10 - M00 * M12;
        float a20 = M10 * M21 - M11 * M20;
        float a21 = M01 * M20 - M00 * M21;
        float a22 = M00 * M11 - M01 * M10;
        float det = M00 * a00 + M01 * a10 + M02 * a20;   // = det(F1)/det(D)
        float idet = rcpa(det);
        float rdet = rsqa(det);
        float nidet = -idet;

        // innovation summaries
        float t0 = zc0 - G0 * ep0;
        float t1 = zc1 - G1 * ep1;
        float t2 = zc2 - G2 * ep2;
        float h0 = G0 * ep0 - 2.0f * zc0;
        float h1 = G1 * ep1 - 2.0f * zc1;
        float h2 = G2 * ep2 - 2.0f * zc2;
        float vDv = zyd + ep0 * h0 + ep1 * h1 + ep2 * h2;

        // jt_u = adj * t (unnormalized);  quad = idet * (S3 t . jt_u)
        float jt0 = a00 * t0 + a01 * t1 + a02 * t2;
        float jt1 = a10 * t0 + a11 * t1 + a12 * t2;
        float jt2 = a20 * t0 + a21 * t1 + a22 * t2;
        float st0 = s00 * t0 + s01 * t1 + s02 * t2;
        float st1 = s01 * t0 + s11 * t1 + s12 * t2;
        float st2 = s02 * t0 + s12 * t1 + s22 * t2;
        float quad = idet * (st0 * jt0 + st1 * jt1 + st2 * jt2);

        float el1 = __expf(Cll + 0.5f * (quad - vDv)) * rdet;

        // eta1 = ep + idet * C (adj t)   (C = P_pred[:, :3])
        float q10 = ep0 + idet * (s00 * jt0 + s01 * jt1 + s02 * jt2);
        float q11 = ep1 + idet * (s01 * jt0 + s11 * jt1 + s12 * jt2);
        float q12 = ep2 + idet * (s02 * jt0 + s12 * jt1 + s22 * jt2);
        float q13 = ep3 + idet * (s03 * jt0 + s13 * jt1 + s23 * jt2);

        // W = C * adj (4x3, unnormalized);  V = W diag(G);  P1 = s - idet * V C^T
        float W00 = s00 * a00 + s01 * a10 + s02 * a20;
        float W01 = s00 * a01 + s01 * a11 + s02 * a21;
        float W02 = s00 * a02 + s01 * a12 + s02 * a22;
        float W10 = s01 * a00 + s11 * a10 + s12 * a20;
        float W11 = s01 * a01 + s11 * a11 + s12 * a21;
        float W12 = s01 * a02 + s11 * a12 + s12 * a22;
        float W20 = s02 * a00 + s12 * a10 + s22 * a20;
        float W21 = s02 * a01 + s12 * a11 + s22 * a21;
        float W22 = s02 * a02 + s12 * a12 + s22 * a22;
        float W30 = s03 * a00 + s13 * a10 + s23 * a20;
        float W31 = s03 * a01 + s13 * a11 + s23 * a21;
        float W32 = s03 * a02 + s13 * a12 + s23 * a22;

        float V00 = W00 * G0, V01 = W01 * G1, V02 = W02 * G2;
        float V10 = W10 * G0, V11 = W11 * G1, V12 = W12 * G2;
        float V20 = W20 * G0, V21 = W21 * G1, V22 = W22 * G2;
        float V30 = W30 * G0, V31 = W31 * G1, V32 = W32 * G2;

        float P1_00 = s00 + nidet * (V00 * s00 + V01 * s01 + V02 * s02);
        float P1_01 = s01 + nidet * (V00 * s01 + V01 * s11 + V02 * s12);
        float P1_02 = s02 + nidet * (V00 * s02 + V01 * s12 + V02 * s22);
        float P1_03 = s03 + nidet * (V00 * s03 + V01 * s13 + V02 * s23);
        float P1_11 = s11 + nidet * (V10 * s01 + V11 * s11 + V12 * s12);
        float P1_12 = s12 + nidet * (V10 * s02 + V11 * s12 + V12 * s22);
        float P1_13 = s13 + nidet * (V10 * s03 + V11 * s13 + V12 * s23);
        float P1_22 = s22 + nidet * (V20 * s02 + V21 * s12 + V22 * s22);
        float P1_23 = s23 + nidet * (V20 * s03 + V21 * s13 + V22 * s23);
        float P1_33 = s33 + nidet * (V30 * s03 + V31 * s13 + V32 * s23);

        // ========== Regime 2: rank-1 Sherman-Morrison ==========
        float beta = 1.0f + s33 * alpha;
        float binv = rcpa(beta);
        float rbeta = rsqa(beta);

        float tau = zsu - alpha * ep3;
        float vDv2 = zyd + ep3 * (alpha * ep3 - 2.0f * zsu);
        float el2 = __expf(Cll - 0.5f * (vDv2 - s33 * tau * tau * binv)) * rbeta;

        float gk = tau * binv;
        float q20 = ep0 + s03 * gk;
        float q21 = ep1 + s13 * gk;
        float q22 = ep2 + s23 * gk;
        float q23 = ep3 + s33 * gk;

        float kap = alpha * binv;                  // P2 = P_pred - (a/b) p p^T
        float k0 = kap * s03, k1 = kap * s13, k2 = kap * s23, k3 = kap * s33;
        float P2_00 = s00 - k0 * s03;
        float P2_01 = s01 - k0 * s13;
        float P2_02 = s02 - k0 * s23;
        float P2_03 = s03 - k0 * s33;
        float P2_11 = s11 - k1 * s13;
        float P2_12 = s12 - k1 * s23;
        float P2_13 = s13 - k1 * s33;
        float P2_22 = s22 - k2 * s23;
        float P2_23 = s23 - k2 * s33;
        float P2_33 = s33 - k3 * s33;

        // ========== IMM mixing (EXACT reference semantics: EPS makes pa+pb < 1) ==========
        float num1 = el1 * (pr0 * p11s);
        float num2 = el2 * (pr0 * (1.0f - p11s) + pr1);
        float marg = num1 + num2 + 1e-9f;
        llacc += __logf(marg);
        float im = rcpa(marg);
        float pa = num1 * im;
        float pb = num2 * im;

        float x0 = pa * q10 + pb * q20;
        float x1 = pa * q11 + pb * q21;
        float x2 = pa * q12 + pb * q22;
        float x3 = pa * q13 + pb * q23;

        float d10 = q10 - x0, d11 = q11 - x1, d12 = q12 - x2, d13 = q13 - x3;
        float d20 = q20 - x0, d21 = q21 - x1, d22 = q22 - x2, d23 = q23 - x3;

        p00  = pa * (P1_00 + d10 * d10) + pb * (P2_00 + d20 * d20);
        p01  = pa * (P1_01 + d10 * d11) + pb * (P2_01 + d20 * d21);
        p02  = pa * (P1_02 + d10 * d12) + pb * (P2_02 + d20 * d22);
        p03  = pa * (P1_03 + d10 * d13) + pb * (P2_03 + d20 * d23);
        p11v = pa * (P1_11 + d11 * d11) + pb * (P2_11 + d21 * d21);
        p12  = pa * (P1_12 + d11 * d12) + pb * (P2_12 + d21 * d22);
        p13  = pa * (P1_13 + d11 * d13) + pb * (P2_13 + d21 * d23);
        p22  = pa * (P1_22 + d12 * d12) + pb * (P2_22 + d22 * d22);
        p23  = pa * (P1_23 + d12 * d13) + pb * (P2_23 + d22 * d23);
        p33  = pa * (P1_33 + d13 * d13) + pb * (P2_33 + d23 * d23);

        // ------------- outputs (inline; latency hidden) -------------
        size_t idx = (size_t)n * NTT + t;
        probs_base[idx * 2]     = pa;
        probs_base[idx * 2 + 1] = pb;

        float* yo = yp_base + idx * 9;
        float pe0 = pa * x0, pe1 = pa * x1, pe2 = pa * x2;
        float a3 = pb * x3;
        yo[0] = pe0 + a3;
        yo[1] = w1 * pe0 + us[1] * a3;
        yo[2] = w2 * pe0 + us[2] * a3;
        yo[3] = pe1 + us[3] * a3;
        yo[4] = w4 * pe1 + us[4] * a3;
        yo[5] = w5 * pe1 + us[5] * a3;
        yo[6] = pe2 + us[6] * a3;
        yo[7] = w7 * pe2 + us[7] * a3;
        yo[8] = w8 * pe2 + us[8] * a3;

        // commit state
        e0 = x0; e1 = x1; e2 = x2; e3 = x3;
        pr0 = pa; pr1 = pb;
#pragma unroll
        for (int o = 0; o < 9; o++) yv[o] = yn[o];
    }

    g_ll[n] = llacc;
}

// Deterministic fixed-order reduction of per-series log-likelihoods.
__global__ void reduce_ll(float* __restrict__ out)
{
    __shared__ double sh[256];
    int t = threadIdx.x;
    double a = 0.0;
#pragma unroll
    for (int i = 0; i < 16; i++) a += (double)g_ll[t * 16 + i];
    sh[t] = a;
    __syncthreads();
#pragma unroll
    for (int s = 128; s > 0; s >>= 1) {
        if (t < s) sh[t] += sh[t + s];
        __syncthreads();
    }
    if (t == 0) out[0] = (float)(-sh[0]);
}

extern "C" void kernel_launch(void* const* d_in, const int* in_sizes, int n_in,
                              void* d_out, int out_size)
{
    (void)in_sizes; (void)n_in; (void)out_size;
    const float* y    = (const float*)d_in[0];
    const float* B1s1 = (const float*)d_in[1];
    const float* B1s2 = (const float*)d_in[2];
    const float* l1f  = (const float*)d_in[3];
    const float* l2f  = (const float*)d_in[4];
    const float* logq = (const float*)d_in[5];
    const float* logr = (const float*)d_in[6];
    const float* g0   = (const float*)d_in[7];
    const float* gc   = (const float*)d_in[8];
    float* out = (float*)d_out;

    kf_main<<<NSER / 32, 32>>>(y, B1s1, B1s2, l1f, l2f, logq, logr, g0, gc, out);
    reduce_ll<<<1, 256>>>(out);
}